// round 12
// baseline (speedup 1.0000x reference)
#include <cuda_runtime.h>
#include <math.h>
#include <cstdint>

// ---------------------------------------------------------------------------
// TimeKAN forward, mma.sync tf32, N-split CTA tiles (128 x 64), 3 CTAs/SM.
// dec writes only d; mkan computes u = tanh.approx^2(d) in registers per
// i-block. Interp GEMMs use ODD Dirichlet rows; even rows closed form (S).
// ---------------------------------------------------------------------------

#define OFF512 0
#define OFF256 8388608
#define OFF128 12582912
#define OFF64  14680064

__device__ uint32_t g_W64 [64 * 64];
__device__ uint32_t g_W128[128 * 128];
__device__ uint32_t g_W256[256 * 256];

__device__ uint32_t g_Ct0[128 * 256];
__device__ uint32_t g_Ct1[128 * 384];
__device__ uint32_t g_Ct2[128 * 512];
__device__ uint32_t g_Ct3[128 * 640];
__device__ float    g_bias[4 * 128];

__device__ float g_d3[128 * 512 * 128];
__device__ float g_d2[128 * 256 * 128];
__device__ float g_d1[128 * 128 * 128];

__device__ float g_oh1[128 * 128 * 128];
__device__ float g_oh2[128 * 256 * 128];
__device__ float g_oh3[128 * 512 * 128];

__device__ uint32_t g_xT [128 * 128 * 512];
__device__ uint32_t g_xT2[128 * 128 * 256];

#define XT256_OFF 0
#define XT128_OFF 4194304
#define XT64_OFF  6291456

#define ASTR 132
#define BSTR 68
#define A_WORDS (32 * ASTR)          // 128-row A tile, 32 frags
#define B_WORDS_H (32 * BSTR)        // 64-row B tile, 32 frags
#define SMEM_BYTES_INTERP ((2 * A_WORDS + 2 * B_WORDS_H + 64) * 4)
#define SMEM_BYTES_MKAN   ((2 * A_WORDS + 2 * B_WORDS_H + 512) * 4)

// ---------------------------------------------------------------------------
__device__ __forceinline__ uint32_t f2tf32(float f) {
    uint32_t r;
    asm("cvt.rna.tf32.f32 %0, %1;" : "=r"(r) : "f"(f));
    return r;
}
__device__ __forceinline__ float u2f(uint32_t u) { return __uint_as_float(u); }

__device__ __forceinline__ float tanha(float x) {
    float r;
    asm("tanh.approx.f32 %0, %1;" : "=f"(r) : "f"(x));
    return r;
}
__device__ __forceinline__ float4 tanh2a_4(float4 v) {
    float4 r;
    r.x = tanha(tanha(v.x)); r.y = tanha(tanha(v.y));
    r.z = tanha(tanha(v.z)); r.w = tanha(tanha(v.w));
    return r;
}

__device__ __forceinline__ void mma_tf32(float c[4], const uint32_t a[4],
                                         uint32_t b0, uint32_t b1) {
    asm volatile(
        "mma.sync.aligned.m16n8k8.row.col.f32.tf32.tf32.f32 "
        "{%0,%1,%2,%3}, {%4,%5,%6,%7}, {%8,%9}, {%0,%1,%2,%3};"
        : "+f"(c[0]), "+f"(c[1]), "+f"(c[2]), "+f"(c[3])
        : "r"(a[0]), "r"(a[1]), "r"(a[2]), "r"(a[3]), "r"(b0), "r"(b1));
}
__device__ __forceinline__ float chebT(int k, float uu) {
    if (k == 1) return uu;
    if (k == 2) return fmaf(2.0f * uu, uu, -1.0f);
    if (k == 3) return uu * fmaf(4.0f * uu, uu, -3.0f);
    float s = uu * uu;
    return fmaf(8.0f * s, s - 1.0f, 1.0f);   // k == 4
}

__device__ __forceinline__ void storeA16(uint32_t* SA, int mf, int kf, int m7,
                                         uint4 v0, uint4 v1, uint4 v2, uint4 v3) {
    uint4* p = (uint4*)(SA + (mf * 4 + kf) * ASTR + m7 * 16);
    p[0] = make_uint4(v0.x, v2.x, v1.x, v3.x);
    p[1] = make_uint4(v0.y, v2.y, v1.y, v3.y);
    p[2] = make_uint4(v0.z, v2.z, v1.z, v3.z);
    p[3] = make_uint4(v0.w, v2.w, v1.w, v3.w);
}
__device__ __forceinline__ void storeB8(uint32_t* SB, int nf, int kf, int n7,
                                        uint4 v0, uint4 v1) {
    uint4* p = (uint4*)(SB + (nf * 4 + kf) * BSTR + n7 * 8);
    p[0] = make_uint4(v0.x, v1.x, v0.y, v1.y);
    p[1] = make_uint4(v0.z, v1.z, v0.w, v1.w);
}

// warp tile 32(M) x 32(N): wm = warp&3 (m), wn = warp>>2 (n half of 64)
__device__ __forceinline__ void mma_tile_h(const uint32_t* SA, const uint32_t* SB,
                                           float acc[2][4][4], int wm, int wn, int lane) {
#pragma unroll
    for (int ks = 0; ks < 4; ks++) {
        uint32_t a[2][4];
#pragma unroll
        for (int r = 0; r < 2; r++) {
            uint4 t = *(const uint4*)(SA + ((wm * 2 + r) * 4 + ks) * ASTR + lane * 4);
            a[r][0] = t.x; a[r][1] = t.y; a[r][2] = t.z; a[r][3] = t.w;
        }
#pragma unroll
        for (int nf = 0; nf < 4; nf++) {
            uint2 bb = *(const uint2*)(SB + ((wn * 4 + nf) * 4 + ks) * BSTR + lane * 2);
            mma_tf32(acc[0][nf], a[0], bb.x, bb.y);
            mma_tf32(acc[1][nf], a[1], bb.x, bb.y);
        }
    }
}

// ---------------------------------------------------------------------------
// interp split staging (A: 128 rows; B: this CTA's 64 channels)
// B thread map: nf = tid>>5, n7 = (tid>>2)&7, kf = tid&3 (one unit/thread)
// ---------------------------------------------------------------------------
struct IRegs { uint4 a0, a1, a2, a3, b0, b1; };

__device__ __forceinline__ void load_iodd(const uint32_t* __restrict__ W,
                                          const uint32_t* __restrict__ xb,
                                          int m0, int L, int amask, int ch,
                                          int tid, IRegs& R) {
    int k0 = ch << 5;
    {
        int kf = tid & 3, m7 = (tid >> 2) & 7, mf = tid >> 5;
        int row = (m0 + mf * 16 + m7) & amask;
        const uint32_t* r0 = W + (size_t)row * L + k0 + kf * 8;
        const uint32_t* r1 = r0 + (size_t)8 * L;
        R.a0 = *(const uint4*)r0; R.a1 = *(const uint4*)(r0 + 4);
        R.a2 = *(const uint4*)r1; R.a3 = *(const uint4*)(r1 + 4);
    }
    {
        int kf = tid & 3, n7 = (tid >> 2) & 7, nf = tid >> 5;
        const uint32_t* rn = xb + (size_t)(nf * 8 + n7) * L + k0 + kf * 8;
        R.b0 = *(const uint4*)rn; R.b1 = *(const uint4*)(rn + 4);
    }
}
__device__ __forceinline__ void store_iodd(uint32_t* SA, uint32_t* SB, int tid,
                                           const IRegs& R, float& s0) {
    int kf = tid & 3, m7 = (tid >> 2) & 7, mf = tid >> 5;
    storeA16(SA, mf, kf, m7, R.a0, R.a1, R.a2, R.a3);
    int n7 = (tid >> 2) & 7, nf = tid >> 5;
    storeB8(SB, nf, kf, n7, R.b0, R.b1);
    s0 += u2f(R.b0.x) - u2f(R.b0.y) + u2f(R.b0.z) - u2f(R.b0.w)
        + u2f(R.b1.x) - u2f(R.b1.y) + u2f(R.b1.z) - u2f(R.b1.w);
}

// ---------------------------------------------------------------------------
// setup kernels
// ---------------------------------------------------------------------------
__device__ __forceinline__ float w_odd(int t, int n, int L) {
    int tt = 2 * t + 1 - 2 * n;
    double th = (double)tt * M_PI / (2.0 * (double)L);
    double gg = sin((double)(L + 1) * th) / sin(th);
    return (float)(gg * 0.25 / (double)L);
}

__global__ void fill_all_kernel(uint32_t* __restrict__ W256,
                                uint32_t* __restrict__ W128,
                                uint32_t* __restrict__ W64) {
    int idx = blockIdx.x * blockDim.x + threadIdx.x;
    if (idx < 65536) {
        int t = idx >> 8, n = idx & 255;
        W256[idx] = f2tf32(w_odd(t, n, 256));
    } else if (idx < 81920) {
        int j = idx - 65536;
        int t = j >> 7, n = j & 127;
        W128[j] = f2tf32(w_odd(t, n, 128));
    } else if (idx < 86016) {
        int j = idx - 81920;
        int t = j >> 6, n = j & 63;
        W64[j] = f2tf32(w_odd(t, n, 64));
    }
}

struct PP { const float* c; uint32_t* Ct; float* bias; int K; };
__global__ void prep_all_kernel(PP p0, PP p1, PP p2, PP p3) {
    int stage = blockIdx.x >> 7;
    int o = blockIdx.x & 127;
    PP p = (stage == 0) ? p0 : (stage == 1) ? p1 : (stage == 2) ? p2 : p3;
    int Kp = p.K * 128;
    for (int cc = threadIdx.x; cc < Kp; cc += blockDim.x) {
        int k = cc >> 7, i = cc & 127;
        p.Ct[(size_t)o * Kp + cc] = f2tf32(p.c[(i * 128 + o) * p.K + k]);
    }
    __shared__ float red[256];
    float s = 0.0f;
    for (int i = threadIdx.x; i < 128; i += blockDim.x) s += p.c[(i * 128 + o) * p.K];
    red[threadIdx.x] = s;
    __syncthreads();
    for (int st = 128; st > 0; st >>= 1) {
        if (threadIdx.x < st) red[threadIdx.x] += red[threadIdx.x + st];
        __syncthreads();
    }
    if (threadIdx.x == 0) p.bias[o] = red[0];
}

__global__ void transpose_all_kernel(const float* __restrict__ x1,
                                     const float* __restrict__ x2,
                                     const float* __restrict__ x3,
                                     uint32_t* __restrict__ xT) {
    __shared__ float t[32][33];
    int bx = blockIdx.x;
    const float* xp;
    uint32_t* xq;
    int L, tidx;
    if (bx < 32)      { L = 256; xp = x1; xq = xT + XT256_OFF; tidx = bx; }
    else if (bx < 48) { L = 128; xp = x2; xq = xT + XT128_OFF; tidx = bx - 32; }
    else              { L = 64;  xp = x3; xq = xT + XT64_OFF;  tidx = bx - 48; }
    int ntiles = L >> 5;
    int n0 = (tidx % ntiles) * 32;
    int o0 = (tidx / ntiles) * 32;
    int b = blockIdx.z;
    int tx = threadIdx.x, ty = threadIdx.y;
    xp += (size_t)b * L * 128;
    xq += (size_t)b * 128 * L;
#pragma unroll
    for (int i = 0; i < 32; i += 8)
        t[ty + i][tx] = xp[(n0 + ty + i) * 128 + o0 + tx];
    __syncthreads();
#pragma unroll
    for (int i = 0; i < 32; i += 8)
        xq[(o0 + ty + i) * L + n0 + tx] = f2tf32(t[tx][ty + i]);
}

// ---------------------------------------------------------------------------
// odd-interp core, N-split: this CTA handles channels [nh*64, nh*64+64)
// ---------------------------------------------------------------------------
__device__ __forceinline__ void interp_odd_core(
    const uint32_t* __restrict__ W, const uint32_t* __restrict__ xT,
    const float* __restrict__ hi, const float* __restrict__ lo,
    float* __restrict__ out, uint32_t* __restrict__ xTout,
    int L, float alpha, int m0, int b, int nh, uint32_t* dynsm)
{
    uint32_t* SA0 = dynsm;
    uint32_t* SA1 = SA0 + A_WORDS;
    uint32_t* SB0 = SA1 + A_WORDS;
    uint32_t* SB1 = SB0 + B_WORDS_H;
    float* Ssh = (float*)(SB1 + B_WORDS_H);   // 64 channels

    int tid = threadIdx.x, lane = tid & 31, warp = tid >> 5;
    int wm = warp & 3, wn = warp >> 2;
    int g = lane >> 2, t4 = lane & 3;
    const uint32_t* xb = xT + ((size_t)b * 128 + nh * 64) * L;
    int amask = L - 1;

    float acc[2][4][4];
#pragma unroll
    for (int r = 0; r < 2; r++)
#pragma unroll
        for (int nf = 0; nf < 4; nf++)
#pragma unroll
            for (int s = 0; s < 4; s++) acc[r][nf][s] = 0.0f;
    float s0 = 0.0f;

    int nch = L >> 5;
    IRegs R;
    load_iodd(W, xb, m0, L, amask, 0, tid, R);
    store_iodd(SA0, SB0, tid, R, s0);
    __syncthreads();
    for (int ch = 0; ch < nch; ch++) {
        int par = ch & 1;
        uint32_t* SAc = par ? SA1 : SA0;
        uint32_t* SBc = par ? SB1 : SB0;
        bool more = (ch + 1 < nch);
        if (more) load_iodd(W, xb, m0, L, amask, ch + 1, tid, R);
        mma_tile_h(SAc, SBc, acc, wm, wn, lane);
        if (more) store_iodd(par ? SA0 : SA1, par ? SB0 : SB1, tid, R, s0);
        __syncthreads();
    }

    // reduce S over kf (lane bits 0..1); local channel = nf*8+n7
    s0 += __shfl_xor_sync(0xFFFFFFFFu, s0, 1);
    s0 += __shfl_xor_sync(0xFFFFFFFFu, s0, 2);
    if ((tid & 3) == 0)
        Ssh[(tid >> 5) * 8 + ((tid >> 2) & 7)] = s0;
    __syncthreads();

    int TL = 2 * L;
    float inv4L = 0.25f / (float)L;
    int cbase = nh * 64 + wn * 32 + t4 * 2;
    int clb   = wn * 32 + t4 * 2;          // local channel base for Ssh
#pragma unroll
    for (int r = 0; r < 2; r++) {
#pragma unroll
        for (int h = 0; h < 2; h++) {
            int tl = m0 + wm * 32 + r * 16 + h * 8 + g;
            if (tl >= L) continue;
            float sgn = (tl & 1) ? -inv4L : inv4L;
            size_t rowe = ((size_t)b * TL + 2 * tl) * 128;
            const float* hie = hi + rowe;
            const float* hio = hi + rowe + 128;
            const float* lor = lo + ((size_t)b * L + tl) * 128;
            float* oute = out + rowe;
            float* outo = out + rowe + 128;
#pragma unroll
            for (int nf = 0; nf < 4; nf++) {
                int c = cbase + nf * 8;
                int cl = clb + nf * 8;
                float a0 = acc[r][nf][h * 2 + 0];
                float a1 = acc[r][nf][h * 2 + 1];
                float2 ho = *(const float2*)(hio + c);
                float vo0 = fmaf(alpha, a0, ho.x);
                float vo1 = fmaf(alpha, a1, ho.y);
                float2 he = *(const float2*)(hie + c);
                float2 xl = *(const float2*)(lor + c);
                float ie0 = fmaf(0.25f, xl.x, sgn * Ssh[cl]);
                float ie1 = fmaf(0.25f, xl.y, sgn * Ssh[cl + 1]);
                float ve0 = fmaf(alpha, ie0, he.x);
                float ve1 = fmaf(alpha, ie1, he.y);
                *(float2*)(oute + c) = make_float2(ve0, ve1);
                *(float2*)(outo + c) = make_float2(vo0, vo1);
                if (xTout) {
                    *(uint2*)(xTout + ((size_t)b * 128 + c) * TL + 2 * tl) =
                        make_uint2(f2tf32(ve0), f2tf32(vo0));
                    *(uint2*)(xTout + ((size_t)b * 128 + c + 1) * TL + 2 * tl) =
                        make_uint2(f2tf32(ve1), f2tf32(vo1));
                }
            }
        }
    }
}

// ---------------------------------------------------------------------------
// batched dec: d = hi - interp(lo). grid 1024.
// ---------------------------------------------------------------------------
struct DP { const uint32_t* W; const uint32_t* xT; const float* hi;
            const float* lo; float* d; int L; };

__global__ __launch_bounds__(256, 3)
void dec_batched_kernel(DP s3, DP s2, DP s1) {
    extern __shared__ uint32_t dynsm[];
    int bx = blockIdx.x;
    DP p;
    int m0, b, nh;
    if (bx < 512)      { p = s3; b = bx >> 2; m0 = ((bx >> 1) & 1) * 128; nh = bx & 1; }
    else if (bx < 768) { int i = bx - 512; p = s2; b = i >> 1; m0 = 0; nh = i & 1; }
    else               { int i = bx - 768; p = s1; b = i >> 1; m0 = 0; nh = i & 1; }
    interp_odd_core(p.W, p.xT, p.hi, p.lo, p.d, nullptr,
                    p.L, -1.0f, m0, b, nh, dynsm);
}

// ---------------------------------------------------------------------------
// mix: out = oh + interp(lo). grid (mtiles*2, B).
// ---------------------------------------------------------------------------
__global__ __launch_bounds__(256, 3)
void mix_odd_kernel(const uint32_t* __restrict__ W, const uint32_t* __restrict__ xT,
                    const float* __restrict__ oh, const float* __restrict__ lo,
                    float* __restrict__ out, uint32_t* __restrict__ xTout, int L) {
    extern __shared__ uint32_t dynsm[];
    interp_odd_core(W, xT, oh, lo, out, xTout,
                    L, 1.0f, (blockIdx.x >> 1) * 128, blockIdx.y, blockIdx.x & 1, dynsm);
}

// ---------------------------------------------------------------------------
// batched mkan, N-split: u in registers per i-block; B = this CTA's 64 Ct rows
// ---------------------------------------------------------------------------
struct MP { const uint32_t* Bm; const float* bias; const float* x;
            const float* w; float* out; uint32_t* xTout; int Kp; int Ntime; };

__global__ __launch_bounds__(256, 3)
void mkan_batched_kernel(MP s3, MP s2, MP s1, MP s0) {
    int bx = blockIdx.x;
    MP p;
    int m0, nh;
    if (bx < 1024)      { p = s3; m0 = (bx >> 1) * 128; nh = bx & 1; }
    else if (bx < 1536) { int i = bx - 1024; p = s2; m0 = (i >> 1) * 128; nh = i & 1; }
    else if (bx < 1792) { int i = bx - 1536; p = s1; m0 = (i >> 1) * 128; nh = i & 1; }
    else                { int i = bx - 1792; p = s0; m0 = (i >> 1) * 128; nh = i & 1; }

    extern __shared__ uint32_t dynsm[];
    uint32_t* SA0 = dynsm;
    uint32_t* SA1 = SA0 + A_WORDS;
    uint32_t* SB0 = SA1 + A_WORDS;
    uint32_t* SB1 = SB0 + B_WORDS_H;
    float* Ws  = (float*)(SB1 + B_WORDS_H);
    float* Bsh = Ws + 384;

    int tid = threadIdx.x, lane = tid & 31, warp = tid >> 5;
    int wm = warp & 3, wn = warp >> 2;
    int g = lane >> 2, t4 = lane & 3;

    for (int j = tid; j < 384; j += 256) Ws[j] = p.w[j];
    if (tid < 128) Bsh[tid] = p.bias[tid];

    float acc[2][4][4];
#pragma unroll
    for (int r = 0; r < 2; r++)
#pragma unroll
        for (int nf = 0; nf < 4; nf++)
#pragma unroll
            for (int s = 0; s < 4; s++) acc[r][nf][s] = 0.0f;

    // staging maps
    int kf = tid & 3, m7 = (tid >> 2) & 7, mf = tid >> 5;
    const float* arow = p.x + (size_t)(m0 + mf * 16 + m7) * 128 + kf * 8;
    int n7b = (tid >> 2) & 7, nfB = tid >> 5;
    const uint32_t* brow = p.Bm + (size_t)(nh * 64 + nfB * 8 + n7b) * p.Kp + kf * 8;

    float4 U0, U1, U2, U3;
    uint4  C0, C1;

    int km1 = (p.Kp >> 7) - 1;      // orders 1..km1 (T_0 in bias)
    int Q = km1 * 4;

    // prologue: ib=0, kk=1
    {
        const float* r0 = arow;
        const float* r1 = r0 + 8 * 128;
        U0 = tanh2a_4(*(const float4*)r0);
        U1 = tanh2a_4(*(const float4*)(r0 + 4));
        U2 = tanh2a_4(*(const float4*)r1);
        U3 = tanh2a_4(*(const float4*)(r1 + 4));
        C0 = *(const uint4*)(brow + 128); C1 = *(const uint4*)(brow + 132);
        uint4 v0, v1, v2, v3;
        v0.x = f2tf32(U0.x); v0.y = f2tf32(U0.y); v0.z = f2tf32(U0.z); v0.w = f2tf32(U0.w);
        v1.x = f2tf32(U1.x); v1.y = f2tf32(U1.y); v1.z = f2tf32(U1.z); v1.w = f2tf32(U1.w);
        v2.x = f2tf32(U2.x); v2.y = f2tf32(U2.y); v2.z = f2tf32(U2.z); v2.w = f2tf32(U2.w);
        v3.x = f2tf32(U3.x); v3.y = f2tf32(U3.y); v3.z = f2tf32(U3.z); v3.w = f2tf32(U3.w);
        storeA16(SA0, mf, kf, m7, v0, v1, v2, v3);
        storeB8(SB0, nfB, kf, n7b, C0, C1);
    }
    __syncthreads();

    int ib = 0, kk = 1;
    for (int q = 0; q < Q; q++) {
        int par = q & 1;
        uint32_t* SAc = par ? SA1 : SA0;
        uint32_t* SBc = par ? SB1 : SB0;
        int nkk = kk + 1, nib = ib;
        if (nkk > km1) { nkk = 1; nib++; }
        bool more = (q + 1 < Q);
        if (more) {
            int k0 = (nkk << 7) + (nib << 5);
            C0 = *(const uint4*)(brow + k0); C1 = *(const uint4*)(brow + k0 + 4);
            if (nkk == 1) {
                const float* r0 = arow + (nib << 5);
                const float* r1 = r0 + 8 * 128;
                U0 = *(const float4*)r0; U1 = *(const float4*)(r0 + 4);
                U2 = *(const float4*)r1; U3 = *(const float4*)(r1 + 4);
            }
        }
        mma_tile_h(SAc, SBc, acc, wm, wn, lane);
        if (more) {
            if (nkk == 1) {
                U0 = tanh2a_4(U0); U1 = tanh2a_4(U1);
                U2 = tanh2a_4(U2); U3 = tanh2a_4(U3);
            }
            uint32_t* SAn = par ? SA0 : SA1;
            uint32_t* SBn = par ? SB0 : SB1;
            uint4 v0, v1, v2, v3;
            v0.x = f2tf32(chebT(nkk, U0.x)); v0.y = f2tf32(chebT(nkk, U0.y));
            v0.z = f2tf32(chebT(nkk, U0.z)); v0.w = f2tf32(chebT(nkk, U0.w));
            v1.x = f2tf32(chebT(nkk, U1.x)); v1.y = f2tf32(chebT(nkk, U1.y));
            v1.z = f2tf32(chebT(nkk, U1.z)); v1.w = f2tf32(chebT(nkk, U1.w));
            v2.x = f2tf32(chebT(nkk, U2.x)); v2.y = f2tf32(chebT(nkk, U2.y));
            v2.z = f2tf32(chebT(nkk, U2.z)); v2.w = f2tf32(chebT(nkk, U2.w));
            v3.x = f2tf32(chebT(nkk, U3.x)); v3.y = f2tf32(chebT(nkk, U3.y));
            v3.z = f2tf32(chebT(nkk, U3.z)); v3.w = f2tf32(chebT(nkk, U3.w));
            storeA16(SAn, mf, kf, m7, v0, v1, v2, v3);
            storeB8(SBn, nfB, kf, n7b, C0, C1);
        }
        __syncthreads();
        kk = nkk; ib = nib;
    }

    int Ntime = p.Ntime;
    int cbase = nh * 64 + wn * 32 + t4 * 2;
#pragma unroll
    for (int r = 0; r < 2; r++) {
#pragma unroll
        for (int h = 0; h < 2; h++) {
            int m = m0 + wm * 32 + r * 16 + h * 8 + g;
            int n = m & (Ntime - 1);
            int bb = m / Ntime;
            const float* xr = p.x + (size_t)m * 128;
            float* orow = p.out + (size_t)m * 128;
            bool hasp = n > 0, hasn = n < (Ntime - 1);
#pragma unroll
            for (int nf = 0; nf < 4; nf++) {
                int c = cbase + nf * 8;
                float v0 = acc[r][nf][h * 2 + 0] + Bsh[c];
                float v1 = acc[r][nf][h * 2 + 1] + Bsh[c + 1];
                float2 cur = *(const float2*)(xr + c);
                float2 prv = hasp ? *(const float2*)(xr + c - 128) : make_float2(0.f, 0.f);
                float2 nxt = hasn ? *(const float2*)(xr + c + 128) : make_float2(0.f, 0.f);
                v0 += cur.x * Ws[c * 3 + 1] + prv.x * Ws[c * 3] + nxt.x * Ws[c * 3 + 2];
                v1 += cur.y * Ws[c * 3 + 4] + prv.y * Ws[c * 3 + 3] + nxt.y * Ws[c * 3 + 5];
                *(float2*)(orow + c) = make_float2(v0, v1);
                if (p.xTout) {
                    p.xTout[((size_t)bb * 128 + c) * Ntime + n]     = f2tf32(v0);
                    p.xTout[((size_t)bb * 128 + c + 1) * Ntime + n] = f2tf32(v1);
                }
            }
        }
    }
}

// ---------------------------------------------------------------------------
extern "C" void kernel_launch(void* const* d_in, const int* in_sizes, int n_in,
                              void* d_out, int out_size) {
    const float* x0 = (const float*)d_in[0];
    const float* x1 = (const float*)d_in[1];
    const float* x2 = (const float*)d_in[2];
    const float* x3 = (const float*)d_in[3];
    const float* c0 = (const float*)d_in[4];
    const float* w0 = (const float*)d_in[5];
    const float* c1 = (const float*)d_in[6];
    const float* w1 = (const float*)d_in[7];
    const float* c2 = (const float*)d_in[8];
    const float* w2 = (const float*)d_in[9];
    const float* c3 = (const float*)d_in[10];
    const float* w3 = (const float*)d_in[11];
    float* out = (float*)d_out;

    uint32_t *pW64, *pW128, *pW256, *pCt0, *pCt1, *pCt2, *pCt3, *pxT, *pxT2;
    float *pbias, *pd3, *pd2, *pd1, *poh1, *poh2, *poh3;
    cudaGetSymbolAddress((void**)&pW64,  g_W64);
    cudaGetSymbolAddress((void**)&pW128, g_W128);
    cudaGetSymbolAddress((void**)&pW256, g_W256);
    cudaGetSymbolAddress((void**)&pCt0,  g_Ct0);
    cudaGetSymbolAddress((void**)&pCt1,  g_Ct1);
    cudaGetSymbolAddress((void**)&pCt2,  g_Ct2);
    cudaGetSymbolAddress((void**)&pCt3,  g_Ct3);
    cudaGetSymbolAddress((void**)&pbias, g_bias);
    cudaGetSymbolAddress((void**)&pd3,   g_d3);
    cudaGetSymbolAddress((void**)&pd2,   g_d2);
    cudaGetSymbolAddress((void**)&pd1,   g_d1);
    cudaGetSymbolAddress((void**)&poh1,  g_oh1);
    cudaGetSymbolAddress((void**)&poh2,  g_oh2);
    cudaGetSymbolAddress((void**)&poh3,  g_oh3);
    cudaGetSymbolAddress((void**)&pxT,   g_xT);
    cudaGetSymbolAddress((void**)&pxT2,  g_xT2);

    cudaFuncSetAttribute(dec_batched_kernel,
                         cudaFuncAttributeMaxDynamicSharedMemorySize, SMEM_BYTES_INTERP);
    cudaFuncSetAttribute(mix_odd_kernel,
                         cudaFuncAttributeMaxDynamicSharedMemorySize, SMEM_BYTES_INTERP);
    cudaFuncSetAttribute(mkan_batched_kernel,
                         cudaFuncAttributeMaxDynamicSharedMemorySize, SMEM_BYTES_MKAN);

    /*0*/ fill_all_kernel<<<(86016 + 255) / 256, 256>>>(pW256, pW128, pW64);
    /*1*/ {
        PP p0 = {c0, pCt0, pbias + 0 * 128, 2};
        PP p1 = {c1, pCt1, pbias + 1 * 128, 3};
        PP p2 = {c2, pCt2, pbias + 2 * 128, 4};
        PP p3 = {c3, pCt3, pbias + 3 * 128, 5};
        prep_all_kernel<<<512, 256>>>(p0, p1, p2, p3);
    }
    /*2*/ transpose_all_kernel<<<dim3(56, 1, 128), dim3(32, 8)>>>(x1, x2, x3, pxT);
    /*3*/ {
        DP s3 = {pW256, pxT + XT256_OFF, x0, x1, pd3, 256};
        DP s2 = {pW128, pxT + XT128_OFF, x1, x2, pd2, 128};
        DP s1 = {pW64,  pxT + XT64_OFF,  x2, x3, pd1, 64};
        dec_batched_kernel<<<1024, 256, SMEM_BYTES_INTERP>>>(s3, s2, s1);
    }
    /*4*/ {
        MP s3 = {pCt3, pbias + 3 * 128, pd3, w3, poh3, nullptr, 640, 512};
        MP s2 = {pCt2, pbias + 2 * 128, pd2, w2, poh2, nullptr, 512, 256};
        MP s1 = {pCt1, pbias + 1 * 128, pd1, w1, poh1, nullptr, 384, 128};
        MP s0 = {pCt0, pbias + 0 * 128, x3, w0, out + OFF64, pxT2, 256, 64};
        mkan_batched_kernel<<<1920, 256, SMEM_BYTES_MKAN>>>(s3, s2, s1, s0);
    }
    /*5*/ mix_odd_kernel<<<dim3(2, 128), 256, SMEM_BYTES_INTERP>>>(
              pW64, pxT2, poh1, out + OFF64, out + OFF128, pxT, 64);
    /*6*/ mix_odd_kernel<<<dim3(2, 128), 256, SMEM_BYTES_INTERP>>>(
              pW128, pxT, poh2, out + OFF128, out + OFF256, pxT2, 128);
    /*7*/ mix_odd_kernel<<<dim3(4, 128), 256, SMEM_BYTES_INTERP>>>(
              pW256, pxT2, poh3, out + OFF256, out + OFF512, nullptr, 256);

    (void)in_sizes; (void)n_in; (void)out_size;
}

// round 14
// speedup vs baseline: 1.0972x; 1.0972x over previous
#include <cuda_runtime.h>
#include <math.h>
#include <cstdint>

// ---------------------------------------------------------------------------
// TimeKAN forward, mma.sync tf32.
// dec + mkan: R11 full-width tiles (128x128, occ 2, crossbar-optimal).
// mix chain: half-width tiles (128x64, occ 3) to fix sub-wave utilization.
// dec writes only d; mkan computes u = tanh.approx^2(d) in registers.
// Interp GEMMs use ODD Dirichlet rows; even rows closed form (S trick).
// ---------------------------------------------------------------------------

#define OFF512 0
#define OFF256 8388608
#define OFF128 12582912
#define OFF64  14680064

__device__ uint32_t g_W64 [64 * 64];
__device__ uint32_t g_W128[128 * 128];
__device__ uint32_t g_W256[256 * 256];

__device__ uint32_t g_Ct0[128 * 256];
__device__ uint32_t g_Ct1[128 * 384];
__device__ uint32_t g_Ct2[128 * 512];
__device__ uint32_t g_Ct3[128 * 640];
__device__ float    g_bias[4 * 128];

__device__ float g_d3[128 * 512 * 128];
__device__ float g_d2[128 * 256 * 128];
__device__ float g_d1[128 * 128 * 128];

__device__ float g_oh1[128 * 128 * 128];
__device__ float g_oh2[128 * 256 * 128];
__device__ float g_oh3[128 * 512 * 128];

__device__ uint32_t g_xT [128 * 128 * 512];
__device__ uint32_t g_xT2[128 * 128 * 256];

#define XT256_OFF 0
#define XT128_OFF 4194304
#define XT64_OFF  6291456

#define ASTR 132
#define BSTR 68
#define A_WORDS (32 * ASTR)          // 128-row A tile
#define B_WORDS (64 * BSTR)          // 128-row B tile (full width)
#define B_WORDS_H (32 * BSTR)        // 64-row B tile (half width)
#define SMEM_BYTES_INTERP ((2 * A_WORDS + 2 * B_WORDS + 128) * 4)
#define SMEM_BYTES_MIX    ((2 * A_WORDS + 2 * B_WORDS_H + 64) * 4)
#define SMEM_BYTES_MKAN   ((2 * A_WORDS + 2 * B_WORDS + 512) * 4)

// ---------------------------------------------------------------------------
__device__ __forceinline__ uint32_t f2tf32(float f) {
    uint32_t r;
    asm("cvt.rna.tf32.f32 %0, %1;" : "=r"(r) : "f"(f));
    return r;
}
__device__ __forceinline__ float u2f(uint32_t u) { return __uint_as_float(u); }

__device__ __forceinline__ float tanha(float x) {
    float r;
    asm("tanh.approx.f32 %0, %1;" : "=f"(r) : "f"(x));
    return r;
}
__device__ __forceinline__ float4 tanh2a_4(float4 v) {
    float4 r;
    r.x = tanha(tanha(v.x)); r.y = tanha(tanha(v.y));
    r.z = tanha(tanha(v.z)); r.w = tanha(tanha(v.w));
    return r;
}

__device__ __forceinline__ void mma_tf32(float c[4], const uint32_t a[4],
                                         uint32_t b0, uint32_t b1) {
    asm volatile(
        "mma.sync.aligned.m16n8k8.row.col.f32.tf32.tf32.f32 "
        "{%0,%1,%2,%3}, {%4,%5,%6,%7}, {%8,%9}, {%0,%1,%2,%3};"
        : "+f"(c[0]), "+f"(c[1]), "+f"(c[2]), "+f"(c[3])
        : "r"(a[0]), "r"(a[1]), "r"(a[2]), "r"(a[3]), "r"(b0), "r"(b1));
}
__device__ __forceinline__ float chebT(int k, float uu) {
    if (k == 1) return uu;
    if (k == 2) return fmaf(2.0f * uu, uu, -1.0f);
    if (k == 3) return uu * fmaf(4.0f * uu, uu, -3.0f);
    float s = uu * uu;
    return fmaf(8.0f * s, s - 1.0f, 1.0f);   // k == 4
}

__device__ __forceinline__ void storeA16(uint32_t* SA, int mf, int kf, int m7,
                                         uint4 v0, uint4 v1, uint4 v2, uint4 v3) {
    uint4* p = (uint4*)(SA + (mf * 4 + kf) * ASTR + m7 * 16);
    p[0] = make_uint4(v0.x, v2.x, v1.x, v3.x);
    p[1] = make_uint4(v0.y, v2.y, v1.y, v3.y);
    p[2] = make_uint4(v0.z, v2.z, v1.z, v3.z);
    p[3] = make_uint4(v0.w, v2.w, v1.w, v3.w);
}
__device__ __forceinline__ void storeB8(uint32_t* SB, int nf, int kf, int n7,
                                        uint4 v0, uint4 v1) {
    uint4* p = (uint4*)(SB + (nf * 4 + kf) * BSTR + n7 * 8);
    p[0] = make_uint4(v0.x, v1.x, v0.y, v1.y);
    p[1] = make_uint4(v0.z, v1.z, v0.w, v1.w);
}

// full-width warp tile 32x64
__device__ __forceinline__ void mma_tile(const uint32_t* SA, const uint32_t* SB,
                                         float acc[2][8][4], int wm, int wn, int lane) {
#pragma unroll
    for (int ks = 0; ks < 4; ks++) {
        uint32_t a[2][4];
#pragma unroll
        for (int r = 0; r < 2; r++) {
            uint4 t = *(const uint4*)(SA + ((wm * 2 + r) * 4 + ks) * ASTR + lane * 4);
            a[r][0] = t.x; a[r][1] = t.y; a[r][2] = t.z; a[r][3] = t.w;
        }
#pragma unroll
        for (int nf = 0; nf < 8; nf++) {
            uint2 bb = *(const uint2*)(SB + ((wn * 8 + nf) * 4 + ks) * BSTR + lane * 2);
            mma_tf32(acc[0][nf], a[0], bb.x, bb.y);
            mma_tf32(acc[1][nf], a[1], bb.x, bb.y);
        }
    }
}
// half-width warp tile 32x32
__device__ __forceinline__ void mma_tile_h(const uint32_t* SA, const uint32_t* SB,
                                           float acc[2][4][4], int wm, int wn, int lane) {
#pragma unroll
    for (int ks = 0; ks < 4; ks++) {
        uint32_t a[2][4];
#pragma unroll
        for (int r = 0; r < 2; r++) {
            uint4 t = *(const uint4*)(SA + ((wm * 2 + r) * 4 + ks) * ASTR + lane * 4);
            a[r][0] = t.x; a[r][1] = t.y; a[r][2] = t.z; a[r][3] = t.w;
        }
#pragma unroll
        for (int nf = 0; nf < 4; nf++) {
            uint2 bb = *(const uint2*)(SB + ((wn * 4 + nf) * 4 + ks) * BSTR + lane * 2);
            mma_tf32(acc[0][nf], a[0], bb.x, bb.y);
            mma_tf32(acc[1][nf], a[1], bb.x, bb.y);
        }
    }
}

// ---------------------------------------------------------------------------
// full-width interp staging (dec)
// ---------------------------------------------------------------------------
struct IRegs { uint4 a0, a1, a2, a3, b00, b01, b10, b11; };

__device__ __forceinline__ void load_iodd(const uint32_t* __restrict__ W,
                                          const uint32_t* __restrict__ xb,
                                          int m0, int L, int amask, int ch,
                                          int tid, IRegs& R) {
    int k0 = ch << 5;
    {
        int kf = tid & 3, m7 = (tid >> 2) & 7, mf = tid >> 5;
        int row = (m0 + mf * 16 + m7) & amask;
        const uint32_t* r0 = W + (size_t)row * L + k0 + kf * 8;
        const uint32_t* r1 = r0 + (size_t)8 * L;
        R.a0 = *(const uint4*)r0; R.a1 = *(const uint4*)(r0 + 4);
        R.a2 = *(const uint4*)r1; R.a3 = *(const uint4*)(r1 + 4);
    }
    {
        int kf = tid & 3, nfl = (tid >> 2) & 1, n7 = (tid >> 3) & 7, nfh = tid >> 6;
        int nf0 = nfh * 2 + nfl;
        const uint32_t* rn0 = xb + (size_t)(nf0 * 8 + n7) * L + k0 + kf * 8;
        const uint32_t* rn1 = xb + (size_t)((nf0 + 8) * 8 + n7) * L + k0 + kf * 8;
        R.b00 = *(const uint4*)rn0; R.b01 = *(const uint4*)(rn0 + 4);
        R.b10 = *(const uint4*)rn1; R.b11 = *(const uint4*)(rn1 + 4);
    }
}
__device__ __forceinline__ void store_iodd(uint32_t* SA, uint32_t* SB, int tid,
                                           const IRegs& R, float& sA, float& sB) {
    int kf = tid & 3, m7 = (tid >> 2) & 7, mf = tid >> 5;
    storeA16(SA, mf, kf, m7, R.a0, R.a1, R.a2, R.a3);
    int nfl = (tid >> 2) & 1, n7 = (tid >> 3) & 7, nfh = tid >> 6;
    int nf0 = nfh * 2 + nfl;
    storeB8(SB, nf0, kf, n7, R.b00, R.b01);
    storeB8(SB, nf0 + 8, kf, n7, R.b10, R.b11);
    sA += u2f(R.b00.x) - u2f(R.b00.y) + u2f(R.b00.z) - u2f(R.b00.w)
        + u2f(R.b01.x) - u2f(R.b01.y) + u2f(R.b01.z) - u2f(R.b01.w);
    sB += u2f(R.b10.x) - u2f(R.b10.y) + u2f(R.b10.z) - u2f(R.b10.w)
        + u2f(R.b11.x) - u2f(R.b11.y) + u2f(R.b11.z) - u2f(R.b11.w);
}

// half-width interp staging (mix)
struct IRegsH { uint4 a0, a1, a2, a3, b0, b1; };

__device__ __forceinline__ void load_ioddh(const uint32_t* __restrict__ W,
                                           const uint32_t* __restrict__ xb,
                                           int m0, int L, int amask, int ch,
                                           int tid, IRegsH& R) {
    int k0 = ch << 5;
    {
        int kf = tid & 3, m7 = (tid >> 2) & 7, mf = tid >> 5;
        int row = (m0 + mf * 16 + m7) & amask;
        const uint32_t* r0 = W + (size_t)row * L + k0 + kf * 8;
        const uint32_t* r1 = r0 + (size_t)8 * L;
        R.a0 = *(const uint4*)r0; R.a1 = *(const uint4*)(r0 + 4);
        R.a2 = *(const uint4*)r1; R.a3 = *(const uint4*)(r1 + 4);
    }
    {
        int kf = tid & 3, n7 = (tid >> 2) & 7, nf = tid >> 5;
        const uint32_t* rn = xb + (size_t)(nf * 8 + n7) * L + k0 + kf * 8;
        R.b0 = *(const uint4*)rn; R.b1 = *(const uint4*)(rn + 4);
    }
}
__device__ __forceinline__ void store_ioddh(uint32_t* SA, uint32_t* SB, int tid,
                                            const IRegsH& R, float& sA) {
    int kf = tid & 3, m7 = (tid >> 2) & 7, mf = tid >> 5;
    storeA16(SA, mf, kf, m7, R.a0, R.a1, R.a2, R.a3);
    int n7 = (tid >> 2) & 7, nf = tid >> 5;
    storeB8(SB, nf, kf, n7, R.b0, R.b1);
    sA += u2f(R.b0.x) - u2f(R.b0.y) + u2f(R.b0.z) - u2f(R.b0.w)
        + u2f(R.b1.x) - u2f(R.b1.y) + u2f(R.b1.z) - u2f(R.b1.w);
}

// ---------------------------------------------------------------------------
// setup kernels
// ---------------------------------------------------------------------------
__device__ __forceinline__ float w_odd(int t, int n, int L) {
    int tt = 2 * t + 1 - 2 * n;
    double th = (double)tt * M_PI / (2.0 * (double)L);
    double gg = sin((double)(L + 1) * th) / sin(th);
    return (float)(gg * 0.25 / (double)L);
}

__global__ void fill_all_kernel(uint32_t* __restrict__ W256,
                                uint32_t* __restrict__ W128,
                                uint32_t* __restrict__ W64) {
    int idx = blockIdx.x * blockDim.x + threadIdx.x;
    if (idx < 65536) {
        int t = idx >> 8, n = idx & 255;
        W256[idx] = f2tf32(w_odd(t, n, 256));
    } else if (idx < 81920) {
        int j = idx - 65536;
        int t = j >> 7, n = j & 127;
        W128[j] = f2tf32(w_odd(t, n, 128));
    } else if (idx < 86016) {
        int j = idx - 81920;
        int t = j >> 6, n = j & 63;
        W64[j] = f2tf32(w_odd(t, n, 64));
    }
}

struct PP { const float* c; uint32_t* Ct; float* bias; int K; };
__global__ void prep_all_kernel(PP p0, PP p1, PP p2, PP p3) {
    int stage = blockIdx.x >> 7;
    int o = blockIdx.x & 127;
    PP p = (stage == 0) ? p0 : (stage == 1) ? p1 : (stage == 2) ? p2 : p3;
    int Kp = p.K * 128;
    for (int cc = threadIdx.x; cc < Kp; cc += blockDim.x) {
        int k = cc >> 7, i = cc & 127;
        p.Ct[(size_t)o * Kp + cc] = f2tf32(p.c[(i * 128 + o) * p.K + k]);
    }
    __shared__ float red[256];
    float s = 0.0f;
    for (int i = threadIdx.x; i < 128; i += blockDim.x) s += p.c[(i * 128 + o) * p.K];
    red[threadIdx.x] = s;
    __syncthreads();
    for (int st = 128; st > 0; st >>= 1) {
        if (threadIdx.x < st) red[threadIdx.x] += red[threadIdx.x + st];
        __syncthreads();
    }
    if (threadIdx.x == 0) p.bias[o] = red[0];
}

__global__ void transpose_all_kernel(const float* __restrict__ x1,
                                     const float* __restrict__ x2,
                                     const float* __restrict__ x3,
                                     uint32_t* __restrict__ xT) {
    __shared__ float t[32][33];
    int bx = blockIdx.x;
    const float* xp;
    uint32_t* xq;
    int L, tidx;
    if (bx < 32)      { L = 256; xp = x1; xq = xT + XT256_OFF; tidx = bx; }
    else if (bx < 48) { L = 128; xp = x2; xq = xT + XT128_OFF; tidx = bx - 32; }
    else              { L = 64;  xp = x3; xq = xT + XT64_OFF;  tidx = bx - 48; }
    int ntiles = L >> 5;
    int n0 = (tidx % ntiles) * 32;
    int o0 = (tidx / ntiles) * 32;
    int b = blockIdx.z;
    int tx = threadIdx.x, ty = threadIdx.y;
    xp += (size_t)b * L * 128;
    xq += (size_t)b * 128 * L;
#pragma unroll
    for (int i = 0; i < 32; i += 8)
        t[ty + i][tx] = xp[(n0 + ty + i) * 128 + o0 + tx];
    __syncthreads();
#pragma unroll
    for (int i = 0; i < 32; i += 8)
        xq[(o0 + ty + i) * L + n0 + tx] = f2tf32(t[tx][ty + i]);
}

// ---------------------------------------------------------------------------
// dec: full-width odd-interp core, d = hi - interp(lo). grid 512, occ 2.
// ---------------------------------------------------------------------------
struct DP { const uint32_t* W; const uint32_t* xT; const float* hi;
            const float* lo; float* d; int L; };

__global__ __launch_bounds__(256, 2)
void dec_batched_kernel(DP s3, DP s2, DP s1) {
    extern __shared__ uint32_t dynsm[];
    int bx = blockIdx.x;
    DP p;
    int m0, b;
    if (bx < 256)      { p = s3; m0 = (bx >> 7) * 128; b = bx & 127; }
    else if (bx < 384) { p = s2; m0 = 0; b = bx - 256; }
    else               { p = s1; m0 = 0; b = bx - 384; }

    uint32_t* SA0 = dynsm;
    uint32_t* SA1 = SA0 + A_WORDS;
    uint32_t* SB0 = SA1 + A_WORDS;
    uint32_t* SB1 = SB0 + B_WORDS;
    float* Ssh = (float*)(SB1 + B_WORDS);

    int tid = threadIdx.x, lane = tid & 31, warp = tid >> 5;
    int wm = warp & 3, wn = warp >> 2;
    int g = lane >> 2, t4 = lane & 3;
    int L = p.L;
    const uint32_t* xb = p.xT + (size_t)b * 128 * L;
    int amask = L - 1;

    float acc[2][8][4];
#pragma unroll
    for (int r = 0; r < 2; r++)
#pragma unroll
        for (int nf = 0; nf < 8; nf++)
#pragma unroll
            for (int s = 0; s < 4; s++) acc[r][nf][s] = 0.0f;
    float sA = 0.0f, sB = 0.0f;

    int nch = L >> 5;
    IRegs R;
    load_iodd(p.W, xb, m0, L, amask, 0, tid, R);
    store_iodd(SA0, SB0, tid, R, sA, sB);
    __syncthreads();
    for (int ch = 0; ch < nch; ch++) {
        int par = ch & 1;
        uint32_t* SAc = par ? SA1 : SA0;
        uint32_t* SBc = par ? SB1 : SB0;
        bool more = (ch + 1 < nch);
        if (more) load_iodd(p.W, xb, m0, L, amask, ch + 1, tid, R);
        mma_tile(SAc, SBc, acc, wm, wn, lane);
        if (more) store_iodd(par ? SA0 : SA1, par ? SB0 : SB1, tid, R, sA, sB);
        __syncthreads();
    }

    sA += __shfl_xor_sync(0xFFFFFFFFu, sA, 1);
    sA += __shfl_xor_sync(0xFFFFFFFFu, sA, 2);
    sB += __shfl_xor_sync(0xFFFFFFFFu, sB, 1);
    sB += __shfl_xor_sync(0xFFFFFFFFu, sB, 2);
    if ((tid & 3) == 0) {
        int nfl = (tid >> 2) & 1, n7 = (tid >> 3) & 7, nfh = tid >> 6;
        Ssh[(nfh * 2 + nfl) * 8 + n7]     = sA;
        Ssh[(nfh * 2 + nfl + 8) * 8 + n7] = sB;
    }
    __syncthreads();

    int TL = 2 * L;
    float inv4L = 0.25f / (float)L;
    int cbase = wn * 64 + t4 * 2;
#pragma unroll
    for (int r = 0; r < 2; r++) {
#pragma unroll
        for (int h = 0; h < 2; h++) {
            int tl = m0 + wm * 32 + r * 16 + h * 8 + g;
            if (tl >= L) continue;
            float sgn = (tl & 1) ? -inv4L : inv4L;
            size_t rowe = ((size_t)b * TL + 2 * tl) * 128;
            const float* hie = p.hi + rowe;
            const float* hio = p.hi + rowe + 128;
            const float* lor = p.lo + ((size_t)b * L + tl) * 128;
            float* oute = p.d + rowe;
            float* outo = p.d + rowe + 128;
#pragma unroll
            for (int nf = 0; nf < 8; nf++) {
                int c = cbase + nf * 8;
                float a0 = acc[r][nf][h * 2 + 0];
                float a1 = acc[r][nf][h * 2 + 1];
                float2 ho = *(const float2*)(hio + c);
                float vo0 = ho.x - a0;
                float vo1 = ho.y - a1;
                float2 he = *(const float2*)(hie + c);
                float2 xl = *(const float2*)(lor + c);
                float ve0 = he.x - fmaf(0.25f, xl.x, sgn * Ssh[c]);
                float ve1 = he.y - fmaf(0.25f, xl.y, sgn * Ssh[c + 1]);
                *(float2*)(oute + c) = make_float2(ve0, ve1);
                *(float2*)(outo + c) = make_float2(vo0, vo1);
            }
        }
    }
}

// ---------------------------------------------------------------------------
// mix: half-width odd-interp core, out = oh + interp(lo). occ 3.
// grid (mtiles*2, B); nh = blockIdx.x & 1.
// ---------------------------------------------------------------------------
__global__ __launch_bounds__(256, 3)
void mix_odd_kernel(const uint32_t* __restrict__ W, const uint32_t* __restrict__ xT,
                    const float* __restrict__ oh, const float* __restrict__ lo,
                    float* __restrict__ out, uint32_t* __restrict__ xTout, int L) {
    extern __shared__ uint32_t dynsm[];
    uint32_t* SA0 = dynsm;
    uint32_t* SA1 = SA0 + A_WORDS;
    uint32_t* SB0 = SA1 + A_WORDS;
    uint32_t* SB1 = SB0 + B_WORDS_H;
    float* Ssh = (float*)(SB1 + B_WORDS_H);

    int m0 = (blockIdx.x >> 1) * 128;
    int nh = blockIdx.x & 1;
    int b = blockIdx.y;

    int tid = threadIdx.x, lane = tid & 31, warp = tid >> 5;
    int wm = warp & 3, wn = warp >> 2;
    int g = lane >> 2, t4 = lane & 3;
    const uint32_t* xb = xT + ((size_t)b * 128 + nh * 64) * L;
    int amask = L - 1;

    float acc[2][4][4];
#pragma unroll
    for (int r = 0; r < 2; r++)
#pragma unroll
        for (int nf = 0; nf < 4; nf++)
#pragma unroll
            for (int s = 0; s < 4; s++) acc[r][nf][s] = 0.0f;
    float sA = 0.0f;

    int nch = L >> 5;
    IRegsH R;
    load_ioddh(W, xb, m0, L, amask, 0, tid, R);
    store_ioddh(SA0, SB0, tid, R, sA);
    __syncthreads();
    for (int ch = 0; ch < nch; ch++) {
        int par = ch & 1;
        uint32_t* SAc = par ? SA1 : SA0;
        uint32_t* SBc = par ? SB1 : SB0;
        bool more = (ch + 1 < nch);
        if (more) load_ioddh(W, xb, m0, L, amask, ch + 1, tid, R);
        mma_tile_h(SAc, SBc, acc, wm, wn, lane);
        if (more) store_ioddh(par ? SA0 : SA1, par ? SB0 : SB1, tid, R, sA);
        __syncthreads();
    }

    sA += __shfl_xor_sync(0xFFFFFFFFu, sA, 1);
    sA += __shfl_xor_sync(0xFFFFFFFFu, sA, 2);
    if ((tid & 3) == 0)
        Ssh[(tid >> 5) * 8 + ((tid >> 2) & 7)] = sA;
    __syncthreads();

    int TL = 2 * L;
    float inv4L = 0.25f / (float)L;
    int cbase = nh * 64 + wn * 32 + t4 * 2;
    int clb   = wn * 32 + t4 * 2;
#pragma unroll
    for (int r = 0; r < 2; r++) {
#pragma unroll
        for (int h = 0; h < 2; h++) {
            int tl = m0 + wm * 32 + r * 16 + h * 8 + g;
            if (tl >= L) continue;
            float sgn = (tl & 1) ? -inv4L : inv4L;
            size_t rowe = ((size_t)b * TL + 2 * tl) * 128;
            const float* hie = oh + rowe;
            const float* hio = oh + rowe + 128;
            const float* lor = lo + ((size_t)b * L + tl) * 128;
            float* oute = out + rowe;
            float* outo = out + rowe + 128;
#pragma unroll
            for (int nf = 0; nf < 4; nf++) {
                int c = cbase + nf * 8;
                int cl = clb + nf * 8;
                float a0 = acc[r][nf][h * 2 + 0];
                float a1 = acc[r][nf][h * 2 + 1];
                float2 ho = *(const float2*)(hio + c);
                float vo0 = a0 + ho.x;
                float vo1 = a1 + ho.y;
                float2 he = *(const float2*)(hie + c);
                float2 xl = *(const float2*)(lor + c);
                float ve0 = he.x + fmaf(0.25f, xl.x, sgn * Ssh[cl]);
                float ve1 = he.y + fmaf(0.25f, xl.y, sgn * Ssh[cl + 1]);
                *(float2*)(oute + c) = make_float2(ve0, ve1);
                *(float2*)(outo + c) = make_float2(vo0, vo1);
                if (xTout) {
                    *(uint2*)(xTout + ((size_t)b * 128 + c) * TL + 2 * tl) =
                        make_uint2(f2tf32(ve0), f2tf32(vo0));
                    *(uint2*)(xTout + ((size_t)b * 128 + c + 1) * TL + 2 * tl) =
                        make_uint2(f2tf32(ve1), f2tf32(vo1));
                }
            }
        }
    }
}

// ---------------------------------------------------------------------------
// batched mkan (R11 full-width): u in registers per i-block, tanh.approx
// ---------------------------------------------------------------------------
struct MP { const uint32_t* Bm; const float* bias; const float* x;
            const float* w; float* out; uint32_t* xTout; int Kp; int Ntime; };

__global__ __launch_bounds__(256, 2)
void mkan_batched_kernel(MP s3, MP s2, MP s1, MP s0) {
    int bx = blockIdx.x;
    MP p;
    int m0;
    if (bx < 512)      { p = s3; m0 = bx * 128; }
    else if (bx < 768) { p = s2; m0 = (bx - 512) * 128; }
    else if (bx < 896) { p = s1; m0 = (bx - 768) * 128; }
    else               { p = s0; m0 = (bx - 896) * 128; }

    extern __shared__ uint32_t dynsm[];
    uint32_t* SA0 = dynsm;
    uint32_t* SA1 = SA0 + A_WORDS;
    uint32_t* SB0 = SA1 + A_WORDS;
    uint32_t* SB1 = SB0 + B_WORDS;
    float* Ws  = (float*)(SB1 + B_WORDS);
    float* Bsh = Ws + 384;

    int tid = threadIdx.x, lane = tid & 31, warp = tid >> 5;
    int wm = warp & 3, wn = warp >> 2;
    int g = lane >> 2, t4 = lane & 3;

    for (int j = tid; j < 384; j += 256) Ws[j] = p.w[j];
    if (tid < 128) Bsh[tid] = p.bias[tid];

    float acc[2][8][4];
#pragma unroll
    for (int r = 0; r < 2; r++)
#pragma unroll
        for (int nf = 0; nf < 8; nf++)
#pragma unroll
            for (int s = 0; s < 4; s++) acc[r][nf][s] = 0.0f;

    int kf = tid & 3, m7 = (tid >> 2) & 7, mf = tid >> 5;
    const float* arow = p.x + (size_t)(m0 + mf * 16 + m7) * 128 + kf * 8;
    int nfl = (tid >> 2) & 1, n7b = (tid >> 3) & 7, nfh = tid >> 6;
    int nf0 = nfh * 2 + nfl;
    const uint32_t* brow0 = p.Bm + (size_t)(nf0 * 8 + n7b) * p.Kp + kf * 8;
    const uint32_t* brow1 = p.Bm + (size_t)((nf0 + 8) * 8 + n7b) * p.Kp + kf * 8;

    float4 U0, U1, U2, U3;
    uint4  C00, C01, C10, C11;

    int km1 = (p.Kp >> 7) - 1;
    int Q = km1 * 4;

    {
        const float* r0 = arow;
        const float* r1 = r0 + 8 * 128;
        U0 = tanh2a_4(*(const float4*)r0);
        U1 = tanh2a_4(*(const float4*)(r0 + 4));
        U2 = tanh2a_4(*(const float4*)r1);
        U3 = tanh2a_4(*(const float4*)(r1 + 4));
        int k0 = 128;
        C00 = *(const uint4*)(brow0 + k0); C01 = *(const uint4*)(brow0 + k0 + 4);
        C10 = *(const uint4*)(brow1 + k0); C11 = *(const uint4*)(brow1 + k0 + 4);
        uint4 v0, v1, v2, v3;
        v0.x = f2tf32(U0.x); v0.y = f2tf32(U0.y); v0.z = f2tf32(U0.z); v0.w = f2tf32(U0.w);
        v1.x = f2tf32(U1.x); v1.y = f2tf32(U1.y); v1.z = f2tf32(U1.z); v1.w = f2tf32(U1.w);
        v2.x = f2tf32(U2.x); v2.y = f2tf32(U2.y); v2.z = f2tf32(U2.z); v2.w = f2tf32(U2.w);
        v3.x = f2tf32(U3.x); v3.y = f2tf32(U3.y); v3.z = f2tf32(U3.z); v3.w = f2tf32(U3.w);
        storeA16(SA0, mf, kf, m7, v0, v1, v2, v3);
        storeB8(SB0, nf0, kf, n7b, C00, C01);
        storeB8(SB0, nf0 + 8, kf, n7b, C10, C11);
    }
    __syncthreads();

    int ib = 0, kk = 1;
    for (int q = 0; q < Q; q++) {
        int par = q & 1;
        uint32_t* SAc = par ? SA1 : SA0;
        uint32_t* SBc = par ? SB1 : SB0;
        int nkk = kk + 1, nib = ib;
        if (nkk > km1) { nkk = 1; nib++; }
        bool more = (q + 1 < Q);
        if (more) {
            int k0 = (nkk << 7) + (nib << 5);
            C00 = *(const uint4*)(brow0 + k0); C01 = *(const uint4*)(brow0 + k0 + 4);
            C10 = *(const uint4*)(brow1 + k0); C11 = *(const uint4*)(brow1 + k0 + 4);
            if (nkk == 1) {
                const float* r0 = arow + (nib << 5);
                const float* r1 = r0 + 8 * 128;
                U0 = *(const float4*)r0; U1 = *(const float4*)(r0 + 4);
                U2 = *(const float4*)r1; U3 = *(const float4*)(r1 + 4);
            }
        }
        mma_tile(SAc, SBc, acc, wm, wn, lane);
        if (more) {
            if (nkk == 1) {
                U0 = tanh2a_4(U0); U1 = tanh2a_4(U1);
                U2 = tanh2a_4(U2); U3 = tanh2a_4(U3);
            }
            uint32_t* SAn = par ? SA0 : SA1;
            uint32_t* SBn = par ? SB0 : SB1;
            uint4 v0, v1, v2, v3;
            v0.x = f2tf32(chebT(nkk, U0.x)); v0.y = f2tf32(chebT(nkk, U0.y));
            v0.z = f2tf32(chebT(nkk, U0.z)); v0.w = f2tf32(chebT(nkk, U0.w));
            v1.x = f2tf32(chebT(nkk, U1.x)); v1.y = f2tf32(chebT(nkk, U1.y));
            v1.z = f2tf32(chebT(nkk, U1.z)); v1.w = f2tf32(chebT(nkk, U1.w));
            v2.x = f2tf32(chebT(nkk, U2.x)); v2.y = f2tf32(chebT(nkk, U2.y));
            v2.z = f2tf32(chebT(nkk, U2.z)); v2.w = f2tf32(chebT(nkk, U2.w));
            v3.x = f2tf32(chebT(nkk, U3.x)); v3.y = f2tf32(chebT(nkk, U3.y));
            v3.z = f2tf32(chebT(nkk, U3.z)); v3.w = f2tf32(chebT(nkk, U3.w));
            storeA16(SAn, mf, kf, m7, v0, v1, v2, v3);
            storeB8(SBn, nf0, kf, n7b, C00, C01);
            storeB8(SBn, nf0 + 8, kf, n7b, C10, C11);
        }
        __syncthreads();
        kk = nkk; ib = nib;
    }

    int Ntime = p.Ntime;
    int cbase = wn * 64 + t4 * 2;
#pragma unroll
    for (int r = 0; r < 2; r++) {
#pragma unroll
        for (int h = 0; h < 2; h++) {
            int m = m0 + wm * 32 + r * 16 + h * 8 + g;
            int n = m & (Ntime - 1);
            int bb = m / Ntime;
            const float* xr = p.x + (size_t)m * 128;
            float* orow = p.out + (size_t)m * 128;
            bool hasp = n > 0, hasn = n < (Ntime - 1);
#pragma unroll
            for (int nf = 0; nf < 8; nf++) {
                int c = cbase + nf * 8;
                float v0 = acc[r][nf][h * 2 + 0] + Bsh[c];
                float v1 = acc[r][nf][h * 2 + 1] + Bsh[c + 1];
                float2 cur = *(const float2*)(xr + c);
                float2 prv = hasp ? *(const float2*)(xr + c - 128) : make_float2(0.f, 0.f);
                float2 nxt = hasn ? *(const float2*)(xr + c + 128) : make_float2(0.f, 0.f);
                v0 += cur.x * Ws[c * 3 + 1] + prv.x * Ws[c * 3] + nxt.x * Ws[c * 3 + 2];
                v1 += cur.y * Ws[c * 3 + 4] + prv.y * Ws[c * 3 + 3] + nxt.y * Ws[c * 3 + 5];
                *(float2*)(orow + c) = make_float2(v0, v1);
                if (p.xTout) {
                    p.xTout[((size_t)bb * 128 + c) * Ntime + n]     = f2tf32(v0);
                    p.xTout[((size_t)bb * 128 + c + 1) * Ntime + n] = f2tf32(v1);
                }
            }
        }
    }
}

// ---------------------------------------------------------------------------
extern "C" void kernel_launch(void* const* d_in, const int* in_sizes, int n_in,
                              void* d_out, int out_size) {
    const float* x0 = (const float*)d_in[0];
    const float* x1 = (const float*)d_in[1];
    const float* x2 = (const float*)d_in[2];
    const float* x3 = (const float*)d_in[3];
    const float* c0 = (const float*)d_in[4];
    const float* w0 = (const float*)d_in[5];
    const float* c1 = (const float*)d_in[6];
    const float* w1 = (const float*)d_in[7];
    const float* c2 = (const float*)d_in[8];
    const float* w2 = (const float*)d_in[9];
    const float* c3 = (const float*)d_in[10];
    const float* w3 = (const float*)d_in[11];
    float* out = (float*)d_out;

    uint32_t *pW64, *pW128, *pW256, *pCt0, *pCt1, *pCt2, *pCt3, *pxT, *pxT2;
    float *pbias, *pd3, *pd2, *pd1, *poh1, *poh2, *poh3;
    cudaGetSymbolAddress((void**)&pW64,  g_W64);
    cudaGetSymbolAddress((void**)&pW128, g_W128);
    cudaGetSymbolAddress((void**)&pW256, g_W256);
    cudaGetSymbolAddress((void**)&pCt0,  g_Ct0);
    cudaGetSymbolAddress((void**)&pCt1,  g_Ct1);
    cudaGetSymbolAddress((void**)&pCt2,  g_Ct2);
    cudaGetSymbolAddress((void**)&pCt3,  g_Ct3);
    cudaGetSymbolAddress((void**)&pbias, g_bias);
    cudaGetSymbolAddress((void**)&pd3,   g_d3);
    cudaGetSymbolAddress((void**)&pd2,   g_d2);
    cudaGetSymbolAddress((void**)&pd1,   g_d1);
    cudaGetSymbolAddress((void**)&poh1,  g_oh1);
    cudaGetSymbolAddress((void**)&poh2,  g_oh2);
    cudaGetSymbolAddress((void**)&poh3,  g_oh3);
    cudaGetSymbolAddress((void**)&pxT,   g_xT);
    cudaGetSymbolAddress((void**)&pxT2,  g_xT2);

    cudaFuncSetAttribute(dec_batched_kernel,
                         cudaFuncAttributeMaxDynamicSharedMemorySize, SMEM_BYTES_INTERP);
    cudaFuncSetAttribute(mix_odd_kernel,
                         cudaFuncAttributeMaxDynamicSharedMemorySize, SMEM_BYTES_MIX);
    cudaFuncSetAttribute(mkan_batched_kernel,
                         cudaFuncAttributeMaxDynamicSharedMemorySize, SMEM_BYTES_MKAN);

    /*0*/ fill_all_kernel<<<(86016 + 255) / 256, 256>>>(pW256, pW128, pW64);
    /*1*/ {
        PP p0 = {c0, pCt0, pbias + 0 * 128, 2};
        PP p1 = {c1, pCt1, pbias + 1 * 128, 3};
        PP p2 = {c2, pCt2, pbias + 2 * 128, 4};
        PP p3 = {c3, pCt3, pbias + 3 * 128, 5};
        prep_all_kernel<<<512, 256>>>(p0, p1, p2, p3);
    }
    /*2*/ transpose_all_kernel<<<dim3(56, 1, 128), dim3(32, 8)>>>(x1, x2, x3, pxT);
    /*3*/ {
        DP s3 = {pW256, pxT + XT256_OFF, x0, x1, pd3, 256};
        DP s2 = {pW128, pxT + XT128_OFF, x1, x2, pd2, 128};
        DP s1 = {pW64,  pxT + XT64_OFF,  x2, x3, pd1, 64};
        dec_batched_kernel<<<512, 256, SMEM_BYTES_INTERP>>>(s3, s2, s1);
    }
    /*4*/ {
        MP s3 = {pCt3, pbias + 3 * 128, pd3, w3, poh3, nullptr, 640, 512};
        MP s2 = {pCt2, pbias + 2 * 128, pd2, w2, poh2, nullptr, 512, 256};
        MP s1 = {pCt1, pbias + 1 * 128, pd1, w1, poh1, nullptr, 384, 128};
        MP s0 = {pCt0, pbias + 0 * 128, x3, w0, out + OFF64, pxT2, 256, 64};
        mkan_batched_kernel<<<960, 256, SMEM_BYTES_MKAN>>>(s3, s2, s1, s0);
    }
    /*5*/ mix_odd_kernel<<<dim3(2, 128), 256, SMEM_BYTES_MIX>>>(
              pW64, pxT2, poh1, out + OFF64, out + OFF128, pxT, 64);
    /*6*/ mix_odd_kernel<<<dim3(2, 128), 256, SMEM_BYTES_MIX>>>(
              pW128, pxT, poh2, out + OFF128, out + OFF256, pxT2, 128);
    /*7*/ mix_odd_kernel<<<dim3(4, 128), 256, SMEM_BYTES_MIX>>>(
              pW256, pxT2, poh3, out + OFF256, out + OFF512, nullptr, 256);

    (void)in_sizes; (void)n_in; (void)out_size;
}

// round 15
// speedup vs baseline: 1.2417x; 1.1317x over previous
#include <cuda_runtime.h>
#include <math.h>
#include <cstdint>

// ---------------------------------------------------------------------------
// TimeKAN forward, mma.sync tf32 (R11 config = measured optimum of tile family)
// + mkan-stage0 merged into the dec launch (fills dec's wave tail, cuts a
//   0.2-wave tail off mkan) + single merged setup launch.
// dec writes only d; mkan computes u = tanh.approx^2(d) in registers per
// i-block. Interp GEMMs use ODD Dirichlet rows; even rows closed form (S).
// ---------------------------------------------------------------------------

#define OFF512 0
#define OFF256 8388608
#define OFF128 12582912
#define OFF64  14680064

__device__ uint32_t g_W64 [64 * 64];
__device__ uint32_t g_W128[128 * 128];
__device__ uint32_t g_W256[256 * 256];

__device__ uint32_t g_Ct0[128 * 256];
__device__ uint32_t g_Ct1[128 * 384];
__device__ uint32_t g_Ct2[128 * 512];
__device__ uint32_t g_Ct3[128 * 640];
__device__ float    g_bias[4 * 128];

__device__ float g_d3[128 * 512 * 128];
__device__ float g_d2[128 * 256 * 128];
__device__ float g_d1[128 * 128 * 128];

__device__ float g_oh1[128 * 128 * 128];
__device__ float g_oh2[128 * 256 * 128];
__device__ float g_oh3[128 * 512 * 128];

__device__ uint32_t g_xT [128 * 128 * 512];
__device__ uint32_t g_xT2[128 * 128 * 256];

#define XT256_OFF 0
#define XT128_OFF 4194304
#define XT64_OFF  6291456

#define ASTR 132
#define BSTR 68
#define A_WORDS (32 * ASTR)
#define B_WORDS (64 * BSTR)
#define SMEM_BYTES_INTERP ((2 * A_WORDS + 2 * B_WORDS + 128) * 4)
#define SMEM_BYTES_MKAN   ((2 * A_WORDS + 2 * B_WORDS + 512) * 4)

// ---------------------------------------------------------------------------
__device__ __forceinline__ uint32_t f2tf32(float f) {
    uint32_t r;
    asm("cvt.rna.tf32.f32 %0, %1;" : "=r"(r) : "f"(f));
    return r;
}
__device__ __forceinline__ float u2f(uint32_t u) { return __uint_as_float(u); }

__device__ __forceinline__ float tanha(float x) {
    float r;
    asm("tanh.approx.f32 %0, %1;" : "=f"(r) : "f"(x));
    return r;
}
__device__ __forceinline__ float4 tanh2a_4(float4 v) {
    float4 r;
    r.x = tanha(tanha(v.x)); r.y = tanha(tanha(v.y));
    r.z = tanha(tanha(v.z)); r.w = tanha(tanha(v.w));
    return r;
}

__device__ __forceinline__ void mma_tf32(float c[4], const uint32_t a[4],
                                         uint32_t b0, uint32_t b1) {
    asm volatile(
        "mma.sync.aligned.m16n8k8.row.col.f32.tf32.tf32.f32 "
        "{%0,%1,%2,%3}, {%4,%5,%6,%7}, {%8,%9}, {%0,%1,%2,%3};"
        : "+f"(c[0]), "+f"(c[1]), "+f"(c[2]), "+f"(c[3])
        : "r"(a[0]), "r"(a[1]), "r"(a[2]), "r"(a[3]), "r"(b0), "r"(b1));
}
__device__ __forceinline__ float chebT(int k, float uu) {
    if (k == 1) return uu;
    if (k == 2) return fmaf(2.0f * uu, uu, -1.0f);
    if (k == 3) return uu * fmaf(4.0f * uu, uu, -3.0f);
    float s = uu * uu;
    return fmaf(8.0f * s, s - 1.0f, 1.0f);   // k == 4
}

__device__ __forceinline__ void storeA16(uint32_t* SA, int mf, int kf, int m7,
                                         uint4 v0, uint4 v1, uint4 v2, uint4 v3) {
    uint4* p = (uint4*)(SA + (mf * 4 + kf) * ASTR + m7 * 16);
    p[0] = make_uint4(v0.x, v2.x, v1.x, v3.x);
    p[1] = make_uint4(v0.y, v2.y, v1.y, v3.y);
    p[2] = make_uint4(v0.z, v2.z, v1.z, v3.z);
    p[3] = make_uint4(v0.w, v2.w, v1.w, v3.w);
}
__device__ __forceinline__ void storeB8(uint32_t* SB, int nf, int kf, int n7,
                                        uint4 v0, uint4 v1) {
    uint4* p = (uint4*)(SB + (nf * 4 + kf) * BSTR + n7 * 8);
    p[0] = make_uint4(v0.x, v1.x, v0.y, v1.y);
    p[1] = make_uint4(v0.z, v1.z, v0.w, v1.w);
}

__device__ __forceinline__ void mma_tile(const uint32_t* SA, const uint32_t* SB,
                                         float acc[2][8][4], int wm, int wn, int lane) {
#pragma unroll
    for (int ks = 0; ks < 4; ks++) {
        uint32_t a[2][4];
#pragma unroll
        for (int r = 0; r < 2; r++) {
            uint4 t = *(const uint4*)(SA + ((wm * 2 + r) * 4 + ks) * ASTR + lane * 4);
            a[r][0] = t.x; a[r][1] = t.y; a[r][2] = t.z; a[r][3] = t.w;
        }
#pragma unroll
        for (int nf = 0; nf < 8; nf++) {
            uint2 bb = *(const uint2*)(SB + ((wn * 8 + nf) * 4 + ks) * BSTR + lane * 2);
            mma_tf32(acc[0][nf], a[0], bb.x, bb.y);
            mma_tf32(acc[1][nf], a[1], bb.x, bb.y);
        }
    }
}

// ---------------------------------------------------------------------------
// interp split staging (full width)
// ---------------------------------------------------------------------------
struct IRegs { uint4 a0, a1, a2, a3, b00, b01, b10, b11; };

__device__ __forceinline__ void load_iodd(const uint32_t* __restrict__ W,
                                          const uint32_t* __restrict__ xb,
                                          int m0, int L, int amask, int ch,
                                          int tid, IRegs& R) {
    int k0 = ch << 5;
    {
        int kf = tid & 3, m7 = (tid >> 2) & 7, mf = tid >> 5;
        int row = (m0 + mf * 16 + m7) & amask;
        const uint32_t* r0 = W + (size_t)row * L + k0 + kf * 8;
        const uint32_t* r1 = r0 + (size_t)8 * L;
        R.a0 = *(const uint4*)r0; R.a1 = *(const uint4*)(r0 + 4);
        R.a2 = *(const uint4*)r1; R.a3 = *(const uint4*)(r1 + 4);
    }
    {
        int kf = tid & 3, nfl = (tid >> 2) & 1, n7 = (tid >> 3) & 7, nfh = tid >> 6;
        int nf0 = nfh * 2 + nfl;
        const uint32_t* rn0 = xb + (size_t)(nf0 * 8 + n7) * L + k0 + kf * 8;
        const uint32_t* rn1 = xb + (size_t)((nf0 + 8) * 8 + n7) * L + k0 + kf * 8;
        R.b00 = *(const uint4*)rn0; R.b01 = *(const uint4*)(rn0 + 4);
        R.b10 = *(const uint4*)rn1; R.b11 = *(const uint4*)(rn1 + 4);
    }
}
__device__ __forceinline__ void store_iodd(uint32_t* SA, uint32_t* SB, int tid,
                                           const IRegs& R, float& sA, float& sB) {
    int kf = tid & 3, m7 = (tid >> 2) & 7, mf = tid >> 5;
    storeA16(SA, mf, kf, m7, R.a0, R.a1, R.a2, R.a3);
    int nfl = (tid >> 2) & 1, n7 = (tid >> 3) & 7, nfh = tid >> 6;
    int nf0 = nfh * 2 + nfl;
    storeB8(SB, nf0, kf, n7, R.b00, R.b01);
    storeB8(SB, nf0 + 8, kf, n7, R.b10, R.b11);
    sA += u2f(R.b00.x) - u2f(R.b00.y) + u2f(R.b00.z) - u2f(R.b00.w)
        + u2f(R.b01.x) - u2f(R.b01.y) + u2f(R.b01.z) - u2f(R.b01.w);
    sB += u2f(R.b10.x) - u2f(R.b10.y) + u2f(R.b10.z) - u2f(R.b10.w)
        + u2f(R.b11.x) - u2f(R.b11.y) + u2f(R.b11.z) - u2f(R.b11.w);
}

// ---------------------------------------------------------------------------
// merged setup kernel: fill W + prep Ct/bias + transpose x1/x2/x3
// ---------------------------------------------------------------------------
__device__ __forceinline__ float w_odd(int t, int n, int L) {
    int tt = 2 * t + 1 - 2 * n;
    double th = (double)tt * M_PI / (2.0 * (double)L);
    double gg = sin((double)(L + 1) * th) / sin(th);
    return (float)(gg * 0.25 / (double)L);
}

struct PP { const float* c; uint32_t* Ct; float* bias; int K; };

__global__ void setup_all_kernel(uint32_t* __restrict__ W256,
                                 uint32_t* __restrict__ W128,
                                 uint32_t* __restrict__ W64,
                                 PP p0, PP p1, PP p2, PP p3,
                                 const float* __restrict__ x1,
                                 const float* __restrict__ x2,
                                 const float* __restrict__ x3,
                                 uint32_t* __restrict__ xT) {
    int bx = blockIdx.x;
    int tid = threadIdx.x;
    if (bx < 336) {
        // fill W matrices
        int idx = bx * 256 + tid;
        if (idx < 65536) {
            int t = idx >> 8, n = idx & 255;
            W256[idx] = f2tf32(w_odd(t, n, 256));
        } else if (idx < 81920) {
            int j = idx - 65536;
            int t = j >> 7, n = j & 127;
            W128[j] = f2tf32(w_odd(t, n, 128));
        } else if (idx < 86016) {
            int j = idx - 81920;
            int t = j >> 6, n = j & 63;
            W64[j] = f2tf32(w_odd(t, n, 64));
        }
        return;
    }
    if (bx < 848) {
        // prep Ct / bias
        int j = bx - 336;
        int stage = j >> 7;
        int o = j & 127;
        PP p = (stage == 0) ? p0 : (stage == 1) ? p1 : (stage == 2) ? p2 : p3;
        int Kp = p.K * 128;
        for (int cc = tid; cc < Kp; cc += blockDim.x) {
            int k = cc >> 7, i = cc & 127;
            p.Ct[(size_t)o * Kp + cc] = f2tf32(p.c[(i * 128 + o) * p.K + k]);
        }
        __shared__ float red[256];
        float s = 0.0f;
        for (int i = tid; i < 128; i += blockDim.x) s += p.c[(i * 128 + o) * p.K];
        red[tid] = s;
        __syncthreads();
        for (int st = 128; st > 0; st >>= 1) {
            if (tid < st) red[tid] += red[tid + st];
            __syncthreads();
        }
        if (tid == 0) p.bias[o] = red[0];
        return;
    }
    // transpose
    {
        __shared__ float t[32][33];
        int j = bx - 848;
        int b = j / 56;
        int sub = j - b * 56;
        const float* xp;
        uint32_t* xq;
        int L, tidx;
        if (sub < 32)      { L = 256; xp = x1; xq = xT + XT256_OFF; tidx = sub; }
        else if (sub < 48) { L = 128; xp = x2; xq = xT + XT128_OFF; tidx = sub - 32; }
        else               { L = 64;  xp = x3; xq = xT + XT64_OFF;  tidx = sub - 48; }
        int ntiles = L >> 5;
        int n0 = (tidx % ntiles) * 32;
        int o0 = (tidx / ntiles) * 32;
        int tx = tid & 31, ty = tid >> 5;
        xp += (size_t)b * L * 128;
        xq += (size_t)b * 128 * L;
#pragma unroll
        for (int i = 0; i < 32; i += 8)
            t[ty + i][tx] = xp[(n0 + ty + i) * 128 + o0 + tx];
        __syncthreads();
#pragma unroll
        for (int i = 0; i < 32; i += 8)
            xq[(o0 + ty + i) * L + n0 + tx] = f2tf32(t[tx][ty + i]);
    }
}

// ---------------------------------------------------------------------------
// full-width odd-interp core (R11)
// ---------------------------------------------------------------------------
__device__ __forceinline__ void interp_odd_core(
    const uint32_t* __restrict__ W, const uint32_t* __restrict__ xT,
    const float* __restrict__ hi, const float* __restrict__ lo,
    float* __restrict__ out, uint32_t* __restrict__ xTout,
    int L, float alpha, int m0, int b, uint32_t* dynsm)
{
    uint32_t* SA0 = dynsm;
    uint32_t* SA1 = SA0 + A_WORDS;
    uint32_t* SB0 = SA1 + A_WORDS;
    uint32_t* SB1 = SB0 + B_WORDS;
    float* Ssh = (float*)(SB1 + B_WORDS);

    int tid = threadIdx.x, lane = tid & 31, warp = tid >> 5;
    int wm = warp & 3, wn = warp >> 2;
    int g = lane >> 2, t4 = lane & 3;
    const uint32_t* xb = xT + (size_t)b * 128 * L;
    int amask = L - 1;

    float acc[2][8][4];
#pragma unroll
    for (int r = 0; r < 2; r++)
#pragma unroll
        for (int nf = 0; nf < 8; nf++)
#pragma unroll
            for (int s = 0; s < 4; s++) acc[r][nf][s] = 0.0f;
    float sA = 0.0f, sB = 0.0f;

    int nch = L >> 5;
    IRegs R;
    load_iodd(W, xb, m0, L, amask, 0, tid, R);
    store_iodd(SA0, SB0, tid, R, sA, sB);
    __syncthreads();
    for (int ch = 0; ch < nch; ch++) {
        int par = ch & 1;
        uint32_t* SAc = par ? SA1 : SA0;
        uint32_t* SBc = par ? SB1 : SB0;
        bool more = (ch + 1 < nch);
        if (more) load_iodd(W, xb, m0, L, amask, ch + 1, tid, R);
        mma_tile(SAc, SBc, acc, wm, wn, lane);
        if (more) store_iodd(par ? SA0 : SA1, par ? SB0 : SB1, tid, R, sA, sB);
        __syncthreads();
    }

    sA += __shfl_xor_sync(0xFFFFFFFFu, sA, 1);
    sA += __shfl_xor_sync(0xFFFFFFFFu, sA, 2);
    sB += __shfl_xor_sync(0xFFFFFFFFu, sB, 1);
    sB += __shfl_xor_sync(0xFFFFFFFFu, sB, 2);
    if ((tid & 3) == 0) {
        int nfl = (tid >> 2) & 1, n7 = (tid >> 3) & 7, nfh = tid >> 6;
        Ssh[(nfh * 2 + nfl) * 8 + n7]     = sA;
        Ssh[(nfh * 2 + nfl + 8) * 8 + n7] = sB;
    }
    __syncthreads();

    int TL = 2 * L;
    float inv4L = 0.25f / (float)L;
    int cbase = wn * 64 + t4 * 2;
#pragma unroll
    for (int r = 0; r < 2; r++) {
#pragma unroll
        for (int h = 0; h < 2; h++) {
            int tl = m0 + wm * 32 + r * 16 + h * 8 + g;
            if (tl >= L) continue;
            float sgn = (tl & 1) ? -inv4L : inv4L;
            size_t rowe = ((size_t)b * TL + 2 * tl) * 128;
            const float* hie = hi + rowe;
            const float* hio = hi + rowe + 128;
            const float* lor = lo + ((size_t)b * L + tl) * 128;
            float* oute = out + rowe;
            float* outo = out + rowe + 128;
#pragma unroll
            for (int nf = 0; nf < 8; nf++) {
                int c = cbase + nf * 8;
                float a0 = acc[r][nf][h * 2 + 0];
                float a1 = acc[r][nf][h * 2 + 1];
                float2 ho = *(const float2*)(hio + c);
                float vo0 = fmaf(alpha, a0, ho.x);
                float vo1 = fmaf(alpha, a1, ho.y);
                float2 he = *(const float2*)(hie + c);
                float2 xl = *(const float2*)(lor + c);
                float ie0 = fmaf(0.25f, xl.x, sgn * Ssh[c]);
                float ie1 = fmaf(0.25f, xl.y, sgn * Ssh[c + 1]);
                float ve0 = fmaf(alpha, ie0, he.x);
                float ve1 = fmaf(alpha, ie1, he.y);
                *(float2*)(oute + c) = make_float2(ve0, ve1);
                *(float2*)(outo + c) = make_float2(vo0, vo1);
                if (xTout) {
                    *(uint2*)(xTout + ((size_t)b * 128 + c) * TL + 2 * tl) =
                        make_uint2(f2tf32(ve0), f2tf32(vo0));
                    *(uint2*)(xTout + ((size_t)b * 128 + c + 1) * TL + 2 * tl) =
                        make_uint2(f2tf32(ve1), f2tf32(vo1));
                }
            }
        }
    }
}

// ---------------------------------------------------------------------------
// mkan core (R11 full-width): u in registers per i-block, tanh.approx
// ---------------------------------------------------------------------------
struct MP { const uint32_t* Bm; const float* bias; const float* x;
            const float* w; float* out; uint32_t* xTout; int Kp; int Ntime; };

__device__ __forceinline__ void mkan_core(const MP& p, int m0, uint32_t* dynsm) {
    uint32_t* SA0 = dynsm;
    uint32_t* SA1 = SA0 + A_WORDS;
    uint32_t* SB0 = SA1 + A_WORDS;
    uint32_t* SB1 = SB0 + B_WORDS;
    float* Ws  = (float*)(SB1 + B_WORDS);
    float* Bsh = Ws + 384;

    int tid = threadIdx.x, lane = tid & 31, warp = tid >> 5;
    int wm = warp & 3, wn = warp >> 2;
    int g = lane >> 2, t4 = lane & 3;

    for (int j = tid; j < 384; j += 256) Ws[j] = p.w[j];
    if (tid < 128) Bsh[tid] = p.bias[tid];

    float acc[2][8][4];
#pragma unroll
    for (int r = 0; r < 2; r++)
#pragma unroll
        for (int nf = 0; nf < 8; nf++)
#pragma unroll
            for (int s = 0; s < 4; s++) acc[r][nf][s] = 0.0f;

    int kf = tid & 3, m7 = (tid >> 2) & 7, mf = tid >> 5;
    const float* arow = p.x + (size_t)(m0 + mf * 16 + m7) * 128 + kf * 8;
    int nfl = (tid >> 2) & 1, n7b = (tid >> 3) & 7, nfh = tid >> 6;
    int nf0 = nfh * 2 + nfl;
    const uint32_t* brow0 = p.Bm + (size_t)(nf0 * 8 + n7b) * p.Kp + kf * 8;
    const uint32_t* brow1 = p.Bm + (size_t)((nf0 + 8) * 8 + n7b) * p.Kp + kf * 8;

    float4 U0, U1, U2, U3;
    uint4  C00, C01, C10, C11;

    int km1 = (p.Kp >> 7) - 1;
    int Q = km1 * 4;

    {
        const float* r0 = arow;
        const float* r1 = r0 + 8 * 128;
        U0 = tanh2a_4(*(const float4*)r0);
        U1 = tanh2a_4(*(const float4*)(r0 + 4));
        U2 = tanh2a_4(*(const float4*)r1);
        U3 = tanh2a_4(*(const float4*)(r1 + 4));
        int k0 = 128;
        C00 = *(const uint4*)(brow0 + k0); C01 = *(const uint4*)(brow0 + k0 + 4);
        C10 = *(const uint4*)(brow1 + k0); C11 = *(const uint4*)(brow1 + k0 + 4);
        uint4 v0, v1, v2, v3;
        v0.x = f2tf32(U0.x); v0.y = f2tf32(U0.y); v0.z = f2tf32(U0.z); v0.w = f2tf32(U0.w);
        v1.x = f2tf32(U1.x); v1.y = f2tf32(U1.y); v1.z = f2tf32(U1.z); v1.w = f2tf32(U1.w);
        v2.x = f2tf32(U2.x); v2.y = f2tf32(U2.y); v2.z = f2tf32(U2.z); v2.w = f2tf32(U2.w);
        v3.x = f2tf32(U3.x); v3.y = f2tf32(U3.y); v3.z = f2tf32(U3.z); v3.w = f2tf32(U3.w);
        storeA16(SA0, mf, kf, m7, v0, v1, v2, v3);
        storeB8(SB0, nf0, kf, n7b, C00, C01);
        storeB8(SB0, nf0 + 8, kf, n7b, C10, C11);
    }
    __syncthreads();

    int ib = 0, kk = 1;
    for (int q = 0; q < Q; q++) {
        int par = q & 1;
        uint32_t* SAc = par ? SA1 : SA0;
        uint32_t* SBc = par ? SB1 : SB0;
        int nkk = kk + 1, nib = ib;
        if (nkk > km1) { nkk = 1; nib++; }
        bool more = (q + 1 < Q);
        if (more) {
            int k0 = (nkk << 7) + (nib << 5);
            C00 = *(const uint4*)(brow0 + k0); C01 = *(const uint4*)(brow0 + k0 + 4);
            C10 = *(const uint4*)(brow1 + k0); C11 = *(const uint4*)(brow1 + k0 + 4);
            if (nkk == 1) {
                const float* r0 = arow + (nib << 5);
                const float* r1 = r0 + 8 * 128;
                U0 = *(const float4*)r0; U1 = *(const float4*)(r0 + 4);
                U2 = *(const float4*)r1; U3 = *(const float4*)(r1 + 4);
            }
        }
        mma_tile(SAc, SBc, acc, wm, wn, lane);
        if (more) {
            if (nkk == 1) {
                U0 = tanh2a_4(U0); U1 = tanh2a_4(U1);
                U2 = tanh2a_4(U2); U3 = tanh2a_4(U3);
            }
            uint32_t* SAn = par ? SA0 : SA1;
            uint32_t* SBn = par ? SB0 : SB1;
            uint4 v0, v1, v2, v3;
            v0.x = f2tf32(chebT(nkk, U0.x)); v0.y = f2tf32(chebT(nkk, U0.y));
            v0.z = f2tf32(chebT(nkk, U0.z)); v0.w = f2tf32(chebT(nkk, U0.w));
            v1.x = f2tf32(chebT(nkk, U1.x)); v1.y = f2tf32(chebT(nkk, U1.y));
            v1.z = f2tf32(chebT(nkk, U1.z)); v1.w = f2tf32(chebT(nkk, U1.w));
            v2.x = f2tf32(chebT(nkk, U2.x)); v2.y = f2tf32(chebT(nkk, U2.y));
            v2.z = f2tf32(chebT(nkk, U2.z)); v2.w = f2tf32(chebT(nkk, U2.w));
            v3.x = f2tf32(chebT(nkk, U3.x)); v3.y = f2tf32(chebT(nkk, U3.y));
            v3.z = f2tf32(chebT(nkk, U3.z)); v3.w = f2tf32(chebT(nkk, U3.w));
            storeA16(SAn, mf, kf, m7, v0, v1, v2, v3);
            storeB8(SBn, nf0, kf, n7b, C00, C01);
            storeB8(SBn, nf0 + 8, kf, n7b, C10, C11);
        }
        __syncthreads();
        kk = nkk; ib = nib;
    }

    int Ntime = p.Ntime;
    int cbase = wn * 64 + t4 * 2;
#pragma unroll
    for (int r = 0; r < 2; r++) {
#pragma unroll
        for (int h = 0; h < 2; h++) {
            int m = m0 + wm * 32 + r * 16 + h * 8 + g;
            int n = m & (Ntime - 1);
            int bb = m / Ntime;
            const float* xr = p.x + (size_t)m * 128;
            float* orow = p.out + (size_t)m * 128;
            bool hasp = n > 0, hasn = n < (Ntime - 1);
#pragma unroll
            for (int nf = 0; nf < 8; nf++) {
                int c = cbase + nf * 8;
                float v0 = acc[r][nf][h * 2 + 0] + Bsh[c];
                float v1 = acc[r][nf][h * 2 + 1] + Bsh[c + 1];
                float2 cur = *(const float2*)(xr + c);
                float2 prv = hasp ? *(const float2*)(xr + c - 128) : make_float2(0.f, 0.f);
                float2 nxt = hasn ? *(const float2*)(xr + c + 128) : make_float2(0.f, 0.f);
                v0 += cur.x * Ws[c * 3 + 1] + prv.x * Ws[c * 3] + nxt.x * Ws[c * 3 + 2];
                v1 += cur.y * Ws[c * 3 + 4] + prv.y * Ws[c * 3 + 3] + nxt.y * Ws[c * 3 + 5];
                *(float2*)(orow + c) = make_float2(v0, v1);
                if (p.xTout) {
                    p.xTout[((size_t)bb * 128 + c) * Ntime + n]     = f2tf32(v0);
                    p.xTout[((size_t)bb * 128 + c + 1) * Ntime + n] = f2tf32(v1);
                }
            }
        }
    }
}

// ---------------------------------------------------------------------------
// dec + mkan-s0 merged launch: bx<512 dec tiles, bx>=512 mkan stage0 tiles
// ---------------------------------------------------------------------------
struct DP { const uint32_t* W; const uint32_t* xT; const float* hi;
            const float* lo; float* d; int L; };

__global__ __launch_bounds__(256, 2)
void dec_s0_kernel(DP q3, DP q2, DP q1, MP ms0) {
    extern __shared__ uint32_t dynsm[];
    int bx = blockIdx.x;
    if (bx >= 512) {
        mkan_core(ms0, (bx - 512) * 128, dynsm);
        return;
    }
    DP p;
    int m0, b;
    if (bx < 256)      { p = q3; m0 = (bx >> 7) * 128; b = bx & 127; }
    else if (bx < 384) { p = q2; m0 = 0; b = bx - 256; }
    else               { p = q1; m0 = 0; b = bx - 384; }
    interp_odd_core(p.W, p.xT, p.hi, p.lo, p.d, nullptr,
                    p.L, -1.0f, m0, b, dynsm);
}

// ---------------------------------------------------------------------------
// mkan stages 3,2,1 (grid 896)
// ---------------------------------------------------------------------------
__global__ __launch_bounds__(256, 2)
void mkan_batched_kernel(MP s3, MP s2, MP s1) {
    extern __shared__ uint32_t dynsm[];
    int bx = blockIdx.x;
    MP p;
    int m0;
    if (bx < 512)      { p = s3; m0 = bx * 128; }
    else if (bx < 768) { p = s2; m0 = (bx - 512) * 128; }
    else               { p = s1; m0 = (bx - 768) * 128; }
    mkan_core(p, m0, dynsm);
}

// ---------------------------------------------------------------------------
// mix: out = oh + interp(lo)  (R11 full-width)
// ---------------------------------------------------------------------------
__global__ __launch_bounds__(256, 2)
void mix_odd_kernel(const uint32_t* __restrict__ W, const uint32_t* __restrict__ xT,
                    const float* __restrict__ oh, const float* __restrict__ lo,
                    float* __restrict__ out, uint32_t* __restrict__ xTout, int L) {
    extern __shared__ uint32_t dynsm[];
    interp_odd_core(W, xT, oh, lo, out, xTout,
                    L, 1.0f, blockIdx.x * 128, blockIdx.y, dynsm);
}

// ---------------------------------------------------------------------------
extern "C" void kernel_launch(void* const* d_in, const int* in_sizes, int n_in,
                              void* d_out, int out_size) {
    const float* x0 = (const float*)d_in[0];
    const float* x1 = (const float*)d_in[1];
    const float* x2 = (const float*)d_in[2];
    const float* x3 = (const float*)d_in[3];
    const float* c0 = (const float*)d_in[4];
    const float* w0 = (const float*)d_in[5];
    const float* c1 = (const float*)d_in[6];
    const float* w1 = (const float*)d_in[7];
    const float* c2 = (const float*)d_in[8];
    const float* w2 = (const float*)d_in[9];
    const float* c3 = (const float*)d_in[10];
    const float* w3 = (const float*)d_in[11];
    float* out = (float*)d_out;

    uint32_t *pW64, *pW128, *pW256, *pCt0, *pCt1, *pCt2, *pCt3, *pxT, *pxT2;
    float *pbias, *pd3, *pd2, *pd1, *poh1, *poh2, *poh3;
    cudaGetSymbolAddress((void**)&pW64,  g_W64);
    cudaGetSymbolAddress((void**)&pW128, g_W128);
    cudaGetSymbolAddress((void**)&pW256, g_W256);
    cudaGetSymbolAddress((void**)&pCt0,  g_Ct0);
    cudaGetSymbolAddress((void**)&pCt1,  g_Ct1);
    cudaGetSymbolAddress((void**)&pCt2,  g_Ct2);
    cudaGetSymbolAddress((void**)&pCt3,  g_Ct3);
    cudaGetSymbolAddress((void**)&pbias, g_bias);
    cudaGetSymbolAddress((void**)&pd3,   g_d3);
    cudaGetSymbolAddress((void**)&pd2,   g_d2);
    cudaGetSymbolAddress((void**)&pd1,   g_d1);
    cudaGetSymbolAddress((void**)&poh1,  g_oh1);
    cudaGetSymbolAddress((void**)&poh2,  g_oh2);
    cudaGetSymbolAddress((void**)&poh3,  g_oh3);
    cudaGetSymbolAddress((void**)&pxT,   g_xT);
    cudaGetSymbolAddress((void**)&pxT2,  g_xT2);

    cudaFuncSetAttribute(dec_s0_kernel,
                         cudaFuncAttributeMaxDynamicSharedMemorySize, SMEM_BYTES_MKAN);
    cudaFuncSetAttribute(mkan_batched_kernel,
                         cudaFuncAttributeMaxDynamicSharedMemorySize, SMEM_BYTES_MKAN);
    cudaFuncSetAttribute(mix_odd_kernel,
                         cudaFuncAttributeMaxDynamicSharedMemorySize, SMEM_BYTES_INTERP);

    /*0*/ {
        PP p0 = {c0, pCt0, pbias + 0 * 128, 2};
        PP p1 = {c1, pCt1, pbias + 1 * 128, 3};
        PP p2 = {c2, pCt2, pbias + 2 * 128, 4};
        PP p3 = {c3, pCt3, pbias + 3 * 128, 5};
        setup_all_kernel<<<8016, 256>>>(pW256, pW128, pW64,
                                        p0, p1, p2, p3, x1, x2, x3, pxT);
    }
    /*1*/ {
        DP q3 = {pW256, pxT + XT256_OFF, x0, x1, pd3, 256};
        DP q2 = {pW128, pxT + XT128_OFF, x1, x2, pd2, 128};
        DP q1 = {pW64,  pxT + XT64_OFF,  x2, x3, pd1, 64};
        MP ms0 = {pCt0, pbias + 0 * 128, x3, w0, out + OFF64, pxT2, 256, 64};
        dec_s0_kernel<<<576, 256, SMEM_BYTES_MKAN>>>(q3, q2, q1, ms0);
    }
    /*2*/ {
        MP s3 = {pCt3, pbias + 3 * 128, pd3, w3, poh3, nullptr, 640, 512};
        MP s2 = {pCt2, pbias + 2 * 128, pd2, w2, poh2, nullptr, 512, 256};
        MP s1 = {pCt1, pbias + 1 * 128, pd1, w1, poh1, nullptr, 384, 128};
        mkan_batched_kernel<<<896, 256, SMEM_BYTES_MKAN>>>(s3, s2, s1);
    }
    /*3*/ mix_odd_kernel<<<dim3(1, 128), 256, SMEM_BYTES_INTERP>>>(
              pW64, pxT2, poh1, out + OFF64, out + OFF128, pxT, 64);
    /*4*/ mix_odd_kernel<<<dim3(1, 128), 256, SMEM_BYTES_INTERP>>>(
              pW128, pxT, poh2, out + OFF128, out + OFF256, pxT2, 128);
    /*5*/ mix_odd_kernel<<<dim3(2, 128), 256, SMEM_BYTES_INTERP>>>(
              pW256, pxT2, poh3, out + OFF256, out + OFF512, nullptr, 256);

    (void)in_sizes; (void)n_in; (void)out_size;
}

// round 16
// speedup vs baseline: 1.2713x; 1.0239x over previous
#include <cuda_runtime.h>
#include <math.h>
#include <cstdint>

// ---------------------------------------------------------------------------
// TimeKAN forward, mma.sync tf32 (R15 + mix64 fused into mkan-stage1).
// dec writes only d; mkan computes u = tanh.approx^2(d) in registers.
// mkan-s1 appends 2 K-chunks (A = full I64 interp matrix, B = m64^T) so its
// epilogue emits the FINAL out128 (oh1 + interp(m64)) and its transpose.
// Interp GEMMs elsewhere use ODD Dirichlet rows; even rows closed form (S).
// ---------------------------------------------------------------------------

#define OFF512 0
#define OFF256 8388608
#define OFF128 12582912
#define OFF64  14680064

__device__ uint32_t g_W64 [64 * 64];
__device__ uint32_t g_W128[128 * 128];
__device__ uint32_t g_W256[256 * 256];
__device__ uint32_t g_W64f[128 * 64];    // FULL I64 matrix (tf32)

__device__ uint32_t g_Ct0[128 * 256];
__device__ uint32_t g_Ct1[128 * 384];
__device__ uint32_t g_Ct2[128 * 512];
__device__ uint32_t g_Ct3[128 * 640];
__device__ float    g_bias[4 * 128];

__device__ float g_d3[128 * 512 * 128];
__device__ float g_d2[128 * 256 * 128];
__device__ float g_d1[128 * 128 * 128];

__device__ float g_oh2[128 * 256 * 128];
__device__ float g_oh3[128 * 512 * 128];

__device__ uint32_t g_xT [128 * 128 * 512];
__device__ uint32_t g_xT2[128 * 128 * 256];

#define XT256_OFF 0
#define XT128_OFF 4194304
#define XT64_OFF  6291456

#define ASTR 132
#define BSTR 68
#define A_WORDS (32 * ASTR)
#define B_WORDS (64 * BSTR)
#define SMEM_BYTES_INTERP ((2 * A_WORDS + 2 * B_WORDS + 128) * 4)
#define SMEM_BYTES_MKAN   ((2 * A_WORDS + 2 * B_WORDS + 512) * 4)

// ---------------------------------------------------------------------------
__device__ __forceinline__ uint32_t f2tf32(float f) {
    uint32_t r;
    asm("cvt.rna.tf32.f32 %0, %1;" : "=r"(r) : "f"(f));
    return r;
}
__device__ __forceinline__ float u2f(uint32_t u) { return __uint_as_float(u); }

__device__ __forceinline__ float tanha(float x) {
    float r;
    asm("tanh.approx.f32 %0, %1;" : "=f"(r) : "f"(x));
    return r;
}
__device__ __forceinline__ float4 tanh2a_4(float4 v) {
    float4 r;
    r.x = tanha(tanha(v.x)); r.y = tanha(tanha(v.y));
    r.z = tanha(tanha(v.z)); r.w = tanha(tanha(v.w));
    return r;
}

__device__ __forceinline__ void mma_tf32(float c[4], const uint32_t a[4],
                                         uint32_t b0, uint32_t b1) {
    asm volatile(
        "mma.sync.aligned.m16n8k8.row.col.f32.tf32.tf32.f32 "
        "{%0,%1,%2,%3}, {%4,%5,%6,%7}, {%8,%9}, {%0,%1,%2,%3};"
        : "+f"(c[0]), "+f"(c[1]), "+f"(c[2]), "+f"(c[3])
        : "r"(a[0]), "r"(a[1]), "r"(a[2]), "r"(a[3]), "r"(b0), "r"(b1));
}
__device__ __forceinline__ float chebT(int k, float uu) {
    if (k == 1) return uu;
    if (k == 2) return fmaf(2.0f * uu, uu, -1.0f);
    if (k == 3) return uu * fmaf(4.0f * uu, uu, -3.0f);
    float s = uu * uu;
    return fmaf(8.0f * s, s - 1.0f, 1.0f);   // k == 4
}

__device__ __forceinline__ void storeA16(uint32_t* SA, int mf, int kf, int m7,
                                         uint4 v0, uint4 v1, uint4 v2, uint4 v3) {
    uint4* p = (uint4*)(SA + (mf * 4 + kf) * ASTR + m7 * 16);
    p[0] = make_uint4(v0.x, v2.x, v1.x, v3.x);
    p[1] = make_uint4(v0.y, v2.y, v1.y, v3.y);
    p[2] = make_uint4(v0.z, v2.z, v1.z, v3.z);
    p[3] = make_uint4(v0.w, v2.w, v1.w, v3.w);
}
__device__ __forceinline__ void storeB8(uint32_t* SB, int nf, int kf, int n7,
                                        uint4 v0, uint4 v1) {
    uint4* p = (uint4*)(SB + (nf * 4 + kf) * BSTR + n7 * 8);
    p[0] = make_uint4(v0.x, v1.x, v0.y, v1.y);
    p[1] = make_uint4(v0.z, v1.z, v0.w, v1.w);
}

__device__ __forceinline__ void mma_tile(const uint32_t* SA, const uint32_t* SB,
                                         float acc[2][8][4], int wm, int wn, int lane) {
#pragma unroll
    for (int ks = 0; ks < 4; ks++) {
        uint32_t a[2][4];
#pragma unroll
        for (int r = 0; r < 2; r++) {
            uint4 t = *(const uint4*)(SA + ((wm * 2 + r) * 4 + ks) * ASTR + lane * 4);
            a[r][0] = t.x; a[r][1] = t.y; a[r][2] = t.z; a[r][3] = t.w;
        }
#pragma unroll
        for (int nf = 0; nf < 8; nf++) {
            uint2 bb = *(const uint2*)(SB + ((wn * 8 + nf) * 4 + ks) * BSTR + lane * 2);
            mma_tf32(acc[0][nf], a[0], bb.x, bb.y);
            mma_tf32(acc[1][nf], a[1], bb.x, bb.y);
        }
    }
}

// ---------------------------------------------------------------------------
// interp split staging (full width)
// ---------------------------------------------------------------------------
struct IRegs { uint4 a0, a1, a2, a3, b00, b01, b10, b11; };

__device__ __forceinline__ void load_iodd(const uint32_t* __restrict__ W,
                                          const uint32_t* __restrict__ xb,
                                          int m0, int L, int amask, int ch,
                                          int tid, IRegs& R) {
    int k0 = ch << 5;
    {
        int kf = tid & 3, m7 = (tid >> 2) & 7, mf = tid >> 5;
        int row = (m0 + mf * 16 + m7) & amask;
        const uint32_t* r0 = W + (size_t)row * L + k0 + kf * 8;
        const uint32_t* r1 = r0 + (size_t)8 * L;
        R.a0 = *(const uint4*)r0; R.a1 = *(const uint4*)(r0 + 4);
        R.a2 = *(const uint4*)r1; R.a3 = *(const uint4*)(r1 + 4);
    }
    {
        int kf = tid & 3, nfl = (tid >> 2) & 1, n7 = (tid >> 3) & 7, nfh = tid >> 6;
        int nf0 = nfh * 2 + nfl;
        const uint32_t* rn0 = xb + (size_t)(nf0 * 8 + n7) * L + k0 + kf * 8;
        const uint32_t* rn1 = xb + (size_t)((nf0 + 8) * 8 + n7) * L + k0 + kf * 8;
        R.b00 = *(const uint4*)rn0; R.b01 = *(const uint4*)(rn0 + 4);
        R.b10 = *(const uint4*)rn1; R.b11 = *(const uint4*)(rn1 + 4);
    }
}
__device__ __forceinline__ void store_iodd(uint32_t* SA, uint32_t* SB, int tid,
                                           const IRegs& R, float& sA, float& sB) {
    int kf = tid & 3, m7 = (tid >> 2) & 7, mf = tid >> 5;
    storeA16(SA, mf, kf, m7, R.a0, R.a1, R.a2, R.a3);
    int nfl = (tid >> 2) & 1, n7 = (tid >> 3) & 7, nfh = tid >> 6;
    int nf0 = nfh * 2 + nfl;
    storeB8(SB, nf0, kf, n7, R.b00, R.b01);
    storeB8(SB, nf0 + 8, kf, n7, R.b10, R.b11);
    sA += u2f(R.b00.x) - u2f(R.b00.y) + u2f(R.b00.z) - u2f(R.b00.w)
        + u2f(R.b01.x) - u2f(R.b01.y) + u2f(R.b01.z) - u2f(R.b01.w);
    sB += u2f(R.b10.x) - u2f(R.b10.y) + u2f(R.b10.z) - u2f(R.b10.w)
        + u2f(R.b11.x) - u2f(R.b11.y) + u2f(R.b11.z) - u2f(R.b11.w);
}

// ---------------------------------------------------------------------------
// merged setup kernel: fill W (odd + full64) + prep Ct/bias + transpose
// ---------------------------------------------------------------------------
__device__ __forceinline__ float w_odd(int t, int n, int L) {
    int tt = 2 * t + 1 - 2 * n;
    double th = (double)tt * M_PI / (2.0 * (double)L);
    double gg = sin((double)(L + 1) * th) / sin(th);
    return (float)(gg * 0.25 / (double)L);
}
__device__ __forceinline__ float w_full(int m, int n, int L) {
    if ((m & 1) == 0) {
        int t = m >> 1;
        float inv4L = 0.25f / (float)L;
        float v = (((t + n) & 1) ? -inv4L : inv4L);
        if (n == t) v += 0.25f;
        return v;
    }
    return w_odd(m >> 1, n, L);
}

struct PP { const float* c; uint32_t* Ct; float* bias; int K; };

__global__ void setup_all_kernel(uint32_t* __restrict__ W256,
                                 uint32_t* __restrict__ W128,
                                 uint32_t* __restrict__ W64,
                                 uint32_t* __restrict__ W64f,
                                 PP p0, PP p1, PP p2, PP p3,
                                 const float* __restrict__ x1,
                                 const float* __restrict__ x2,
                                 const float* __restrict__ x3,
                                 uint32_t* __restrict__ xT) {
    int bx = blockIdx.x;
    int tid = threadIdx.x;
    if (bx < 368) {
        int idx = bx * 256 + tid;
        if (idx < 65536) {
            int t = idx >> 8, n = idx & 255;
            W256[idx] = f2tf32(w_odd(t, n, 256));
        } else if (idx < 81920) {
            int j = idx - 65536;
            int t = j >> 7, n = j & 127;
            W128[j] = f2tf32(w_odd(t, n, 128));
        } else if (idx < 86016) {
            int j = idx - 81920;
            int t = j >> 6, n = j & 63;
            W64[j] = f2tf32(w_odd(t, n, 64));
        } else if (idx < 94208) {
            int j = idx - 86016;
            int m = j >> 6, n = j & 63;
            W64f[j] = f2tf32(w_full(m, n, 64));
        }
        return;
    }
    if (bx < 880) {
        int j = bx - 368;
        int stage = j >> 7;
        int o = j & 127;
        PP p = (stage == 0) ? p0 : (stage == 1) ? p1 : (stage == 2) ? p2 : p3;
        int Kp = p.K * 128;
        for (int cc = tid; cc < Kp; cc += blockDim.x) {
            int k = cc >> 7, i = cc & 127;
            p.Ct[(size_t)o * Kp + cc] = f2tf32(p.c[(i * 128 + o) * p.K + k]);
        }
        __shared__ float red[256];
        float s = 0.0f;
        for (int i = tid; i < 128; i += blockDim.x) s += p.c[(i * 128 + o) * p.K];
        red[tid] = s;
        __syncthreads();
        for (int st = 128; st > 0; st >>= 1) {
            if (tid < st) red[tid] += red[tid + st];
            __syncthreads();
        }
        if (tid == 0) p.bias[o] = red[0];
        return;
    }
    {
        __shared__ float t[32][33];
        int j = bx - 880;
        int b = j / 56;
        int sub = j - b * 56;
        const float* xp;
        uint32_t* xq;
        int L, tidx;
        if (sub < 32)      { L = 256; xp = x1; xq = xT + XT256_OFF; tidx = sub; }
        else if (sub < 48) { L = 128; xp = x2; xq = xT + XT128_OFF; tidx = sub - 32; }
        else               { L = 64;  xp = x3; xq = xT + XT64_OFF;  tidx = sub - 48; }
        int ntiles = L >> 5;
        int n0 = (tidx % ntiles) * 32;
        int o0 = (tidx / ntiles) * 32;
        int tx = tid & 31, ty = tid >> 5;
        xp += (size_t)b * L * 128;
        xq += (size_t)b * 128 * L;
#pragma unroll
        for (int i = 0; i < 32; i += 8)
            t[ty + i][tx] = xp[(n0 + ty + i) * 128 + o0 + tx];
        __syncthreads();
#pragma unroll
        for (int i = 0; i < 32; i += 8)
            xq[(o0 + ty + i) * L + n0 + tx] = f2tf32(t[tx][ty + i]);
    }
}

// ---------------------------------------------------------------------------
// full-width odd-interp core
// ---------------------------------------------------------------------------
__device__ __forceinline__ void interp_odd_core(
    const uint32_t* __restrict__ W, const uint32_t* __restrict__ xT,
    const float* __restrict__ hi, const float* __restrict__ lo,
    float* __restrict__ out, uint32_t* __restrict__ xTout,
    int L, float alpha, int m0, int b, uint32_t* dynsm)
{
    uint32_t* SA0 = dynsm;
    uint32_t* SA1 = SA0 + A_WORDS;
    uint32_t* SB0 = SA1 + A_WORDS;
    uint32_t* SB1 = SB0 + B_WORDS;
    float* Ssh = (float*)(SB1 + B_WORDS);

    int tid = threadIdx.x, lane = tid & 31, warp = tid >> 5;
    int wm = warp & 3, wn = warp >> 2;
    int g = lane >> 2, t4 = lane & 3;
    const uint32_t* xb = xT + (size_t)b * 128 * L;
    int amask = L - 1;

    float acc[2][8][4];
#pragma unroll
    for (int r = 0; r < 2; r++)
#pragma unroll
        for (int nf = 0; nf < 8; nf++)
#pragma unroll
            for (int s = 0; s < 4; s++) acc[r][nf][s] = 0.0f;
    float sA = 0.0f, sB = 0.0f;

    int nch = L >> 5;
    IRegs R;
    load_iodd(W, xb, m0, L, amask, 0, tid, R);
    store_iodd(SA0, SB0, tid, R, sA, sB);
    __syncthreads();
    for (int ch = 0; ch < nch; ch++) {
        int par = ch & 1;
        uint32_t* SAc = par ? SA1 : SA0;
        uint32_t* SBc = par ? SB1 : SB0;
        bool more = (ch + 1 < nch);
        if (more) load_iodd(W, xb, m0, L, amask, ch + 1, tid, R);
        mma_tile(SAc, SBc, acc, wm, wn, lane);
        if (more) store_iodd(par ? SA0 : SA1, par ? SB0 : SB1, tid, R, sA, sB);
        __syncthreads();
    }

    sA += __shfl_xor_sync(0xFFFFFFFFu, sA, 1);
    sA += __shfl_xor_sync(0xFFFFFFFFu, sA, 2);
    sB += __shfl_xor_sync(0xFFFFFFFFu, sB, 1);
    sB += __shfl_xor_sync(0xFFFFFFFFu, sB, 2);
    if ((tid & 3) == 0) {
        int nfl = (tid >> 2) & 1, n7 = (tid >> 3) & 7, nfh = tid >> 6;
        Ssh[(nfh * 2 + nfl) * 8 + n7]     = sA;
        Ssh[(nfh * 2 + nfl + 8) * 8 + n7] = sB;
    }
    __syncthreads();

    int TL = 2 * L;
    float inv4L = 0.25f / (float)L;
    int cbase = wn * 64 + t4 * 2;
#pragma unroll
    for (int r = 0; r < 2; r++) {
#pragma unroll
        for (int h = 0; h < 2; h++) {
            int tl = m0 + wm * 32 + r * 16 + h * 8 + g;
            if (tl >= L) continue;
            float sgn = (tl & 1) ? -inv4L : inv4L;
            size_t rowe = ((size_t)b * TL + 2 * tl) * 128;
            const float* hie = hi + rowe;
            const float* hio = hi + rowe + 128;
            const float* lor = lo + ((size_t)b * L + tl) * 128;
            float* oute = out + rowe;
            float* outo = out + rowe + 128;
#pragma unroll
            for (int nf = 0; nf < 8; nf++) {
                int c = cbase + nf * 8;
                float a0 = acc[r][nf][h * 2 + 0];
                float a1 = acc[r][nf][h * 2 + 1];
                float2 ho = *(const float2*)(hio + c);
                float vo0 = fmaf(alpha, a0, ho.x);
                float vo1 = fmaf(alpha, a1, ho.y);
                float2 he = *(const float2*)(hie + c);
                float2 xl = *(const float2*)(lor + c);
                float ie0 = fmaf(0.25f, xl.x, sgn * Ssh[c]);
                float ie1 = fmaf(0.25f, xl.y, sgn * Ssh[c + 1]);
                float ve0 = fmaf(alpha, ie0, he.x);
                float ve1 = fmaf(alpha, ie1, he.y);
                *(float2*)(oute + c) = make_float2(ve0, ve1);
                *(float2*)(outo + c) = make_float2(vo0, vo1);
                if (xTout) {
                    *(uint2*)(xTout + ((size_t)b * 128 + c) * TL + 2 * tl) =
                        make_uint2(f2tf32(ve0), f2tf32(vo0));
                    *(uint2*)(xTout + ((size_t)b * 128 + c + 1) * TL + 2 * tl) =
                        make_uint2(f2tf32(ve1), f2tf32(vo1));
                }
            }
        }
    }
}

// ---------------------------------------------------------------------------
// mkan core: u in registers per i-block; optional 2 extra interp chunks
// (A = Wx full-interp 128x64, B = xbT 128x64) accumulated into acc.
// ---------------------------------------------------------------------------
struct MP { const uint32_t* Bm; const float* bias; const float* x;
            const float* w; float* out; uint32_t* xTout; int Kp; int Ntime; };

__device__ __forceinline__ void mkan_core(const MP& p, int m0, uint32_t* dynsm,
                                          const uint32_t* __restrict__ Wx,
                                          const uint32_t* __restrict__ xbT) {
    uint32_t* SA0 = dynsm;
    uint32_t* SA1 = SA0 + A_WORDS;
    uint32_t* SB0 = SA1 + A_WORDS;
    uint32_t* SB1 = SB0 + B_WORDS;
    float* Ws  = (float*)(SB1 + B_WORDS);
    float* Bsh = Ws + 384;

    int tid = threadIdx.x, lane = tid & 31, warp = tid >> 5;
    int wm = warp & 3, wn = warp >> 2;
    int g = lane >> 2, t4 = lane & 3;

    for (int j = tid; j < 384; j += 256) Ws[j] = p.w[j];
    if (tid < 128) Bsh[tid] = p.bias[tid];

    float acc[2][8][4];
#pragma unroll
    for (int r = 0; r < 2; r++)
#pragma unroll
        for (int nf = 0; nf < 8; nf++)
#pragma unroll
            for (int s = 0; s < 4; s++) acc[r][nf][s] = 0.0f;

    int kf = tid & 3, m7 = (tid >> 2) & 7, mf = tid >> 5;
    const float* arow = p.x + (size_t)(m0 + mf * 16 + m7) * 128 + kf * 8;
    int nfl = (tid >> 2) & 1, n7b = (tid >> 3) & 7, nfh = tid >> 6;
    int nf0 = nfh * 2 + nfl;
    const uint32_t* brow0 = p.Bm + (size_t)(nf0 * 8 + n7b) * p.Kp + kf * 8;
    const uint32_t* brow1 = p.Bm + (size_t)((nf0 + 8) * 8 + n7b) * p.Kp + kf * 8;

    float4 U0, U1, U2, U3;
    uint4  C00, C01, C10, C11;

    int km1 = (p.Kp >> 7) - 1;
    int Q = km1 * 4;
    int Qtot = Q + (Wx ? 2 : 0);

    {   // prologue: chunk 0 (mkan type: ib=0, kk=1)
        const float* r0 = arow;
        const float* r1 = r0 + 8 * 128;
        U0 = tanh2a_4(*(const float4*)r0);
        U1 = tanh2a_4(*(const float4*)(r0 + 4));
        U2 = tanh2a_4(*(const float4*)r1);
        U3 = tanh2a_4(*(const float4*)(r1 + 4));
        int k0 = 128;
        C00 = *(const uint4*)(brow0 + k0); C01 = *(const uint4*)(brow0 + k0 + 4);
        C10 = *(const uint4*)(brow1 + k0); C11 = *(const uint4*)(brow1 + k0 + 4);
        uint4 v0, v1, v2, v3;
        v0.x = f2tf32(U0.x); v0.y = f2tf32(U0.y); v0.z = f2tf32(U0.z); v0.w = f2tf32(U0.w);
        v1.x = f2tf32(U1.x); v1.y = f2tf32(U1.y); v1.z = f2tf32(U1.z); v1.w = f2tf32(U1.w);
        v2.x = f2tf32(U2.x); v2.y = f2tf32(U2.y); v2.z = f2tf32(U2.z); v2.w = f2tf32(U2.w);
        v3.x = f2tf32(U3.x); v3.y = f2tf32(U3.y); v3.z = f2tf32(U3.z); v3.w = f2tf32(U3.w);
        storeA16(SA0, mf, kf, m7, v0, v1, v2, v3);
        storeB8(SB0, nf0, kf, n7b, C00, C01);
        storeB8(SB0, nf0 + 8, kf, n7b, C10, C11);
    }
    __syncthreads();

    int ib = 0, kk = 1;
    for (int q = 0; q < Qtot; q++) {
        int par = q & 1;
        uint32_t* SAc = par ? SA1 : SA0;
        uint32_t* SBc = par ? SB1 : SB0;
        int nq = q + 1;
        bool more = (nq < Qtot);
        bool nExt = (nq >= Q);
        int nkk = kk, nib = ib;
        if (more) {
            if (!nExt) {
                nkk = kk + 1; nib = ib;
                if (nkk > km1) { nkk = 1; nib++; }
                int k0 = (nkk << 7) + (nib << 5);
                C00 = *(const uint4*)(brow0 + k0); C01 = *(const uint4*)(brow0 + k0 + 4);
                C10 = *(const uint4*)(brow1 + k0); C11 = *(const uint4*)(brow1 + k0 + 4);
                if (nkk == 1) {
                    const float* r0 = arow + (nib << 5);
                    const float* r1 = r0 + 8 * 128;
                    U0 = *(const float4*)r0; U1 = *(const float4*)(r0 + 4);
                    U2 = *(const float4*)r1; U3 = *(const float4*)(r1 + 4);
                }
            } else {
                int ke = nq - Q;   // 0 or 1
                const uint32_t* wr0 = Wx + (size_t)(mf * 16 + m7) * 64 + ke * 32 + kf * 8;
                const uint32_t* wr1 = wr0 + 8 * 64;
                C00 = *(const uint4*)wr0; C01 = *(const uint4*)(wr0 + 4);
                C10 = *(const uint4*)wr1; C11 = *(const uint4*)(wr1 + 4);
                const uint32_t* xr0 = xbT + (size_t)(nf0 * 8 + n7b) * 64 + ke * 32 + kf * 8;
                const uint32_t* xr1 = xbT + (size_t)((nf0 + 8) * 8 + n7b) * 64 + ke * 32 + kf * 8;
                uint4 e0 = *(const uint4*)xr0, e1 = *(const uint4*)(xr0 + 4);
                uint4 e2 = *(const uint4*)xr1, e3 = *(const uint4*)(xr1 + 4);
                U0 = make_float4(u2f(e0.x), u2f(e0.y), u2f(e0.z), u2f(e0.w));
                U1 = make_float4(u2f(e1.x), u2f(e1.y), u2f(e1.z), u2f(e1.w));
                U2 = make_float4(u2f(e2.x), u2f(e2.y), u2f(e2.z), u2f(e2.w));
                U3 = make_float4(u2f(e3.x), u2f(e3.y), u2f(e3.z), u2f(e3.w));
            }
        }
        mma_tile(SAc, SBc, acc, wm, wn, lane);
        if (more) {
            uint32_t* SAn = par ? SA0 : SA1;
            uint32_t* SBn = par ? SB0 : SB1;
            if (!nExt) {
                if (nkk == 1) {
                    U0 = tanh2a_4(U0); U1 = tanh2a_4(U1);
                    U2 = tanh2a_4(U2); U3 = tanh2a_4(U3);
                }
                uint4 v0, v1, v2, v3;
                v0.x = f2tf32(chebT(nkk, U0.x)); v0.y = f2tf32(chebT(nkk, U0.y));
                v0.z = f2tf32(chebT(nkk, U0.z)); v0.w = f2tf32(chebT(nkk, U0.w));
                v1.x = f2tf32(chebT(nkk, U1.x)); v1.y = f2tf32(chebT(nkk, U1.y));
                v1.z = f2tf32(chebT(nkk, U1.z)); v1.w = f2tf32(chebT(nkk, U1.w));
                v2.x = f2tf32(chebT(nkk, U2.x)); v2.y = f2tf32(chebT(nkk, U2.y));
                v2.z = f2tf32(chebT(nkk, U2.z)); v2.w = f2tf32(chebT(nkk, U2.w));
                v3.x = f2tf32(chebT(nkk, U3.x)); v3.y = f2tf32(chebT(nkk, U3.y));
                v3.z = f2tf32(chebT(nkk, U3.z)); v3.w = f2tf32(chebT(nkk, U3.w));
                storeA16(SAn, mf, kf, m7, v0, v1, v2, v3);
                storeB8(SBn, nf0, kf, n7b, C00, C01);
                storeB8(SBn, nf0 + 8, kf, n7b, C10, C11);
                kk = nkk; ib = nib;
            } else {
                storeA16(SAn, mf, kf, m7, C00, C01, C10, C11);
                uint4 f0 = make_uint4(__float_as_uint(U0.x), __float_as_uint(U0.y),
                                      __float_as_uint(U0.z), __float_as_uint(U0.w));
                uint4 f1 = make_uint4(__float_as_uint(U1.x), __float_as_uint(U1.y),
                                      __float_as_uint(U1.z), __float_as_uint(U1.w));
                uint4 f2 = make_uint4(__float_as_uint(U2.x), __float_as_uint(U2.y),
                                      __float_as_uint(U2.z), __float_as_uint(U2.w));
                uint4 f3 = make_uint4(__float_as_uint(U3.x), __float_as_uint(U3.y),
                                      __float_as_uint(U3.z), __float_as_uint(U3.w));
                storeB8(SBn, nf0, kf, n7b, f0, f1);
                storeB8(SBn, nf0 + 8, kf, n7b, f2, f3);
            }
        }
        __syncthreads();
    }

    int Ntime = p.Ntime;
    int cbase = wn * 64 + t4 * 2;
#pragma unroll
    for (int r = 0; r < 2; r++) {
#pragma unroll
        for (int h = 0; h < 2; h++) {
            int m = m0 + wm * 32 + r * 16 + h * 8 + g;
            int n = m & (Ntime - 1);
            int bb = m / Ntime;
            const float* xr = p.x + (size_t)m * 128;
            float* orow = p.out + (size_t)m * 128;
            bool hasp = n > 0, hasn = n < (Ntime - 1);
#pragma unroll
            for (int nf = 0; nf < 8; nf++) {
                int c = cbase + nf * 8;
                float v0 = acc[r][nf][h * 2 + 0] + Bsh[c];
                float v1 = acc[r][nf][h * 2 + 1] + Bsh[c + 1];
                float2 cur = *(const float2*)(xr + c);
                float2 prv = hasp ? *(const float2*)(xr + c - 128) : make_float2(0.f, 0.f);
                float2 nxt = hasn ? *(const float2*)(xr + c + 128) : make_float2(0.f, 0.f);
                v0 += cur.x * Ws[c * 3 + 1] + prv.x * Ws[c * 3] + nxt.x * Ws[c * 3 + 2];
                v1 += cur.y * Ws[c * 3 + 4] + prv.y * Ws[c * 3 + 3] + nxt.y * Ws[c * 3 + 5];
                *(float2*)(orow + c) = make_float2(v0, v1);
                if (p.xTout) {
                    p.xTout[((size_t)bb * 128 + c) * Ntime + n]     = f2tf32(v0);
                    p.xTout[((size_t)bb * 128 + c + 1) * Ntime + n] = f2tf32(v1);
                }
            }
        }
    }
}

// ---------------------------------------------------------------------------
// dec + mkan-s0 merged launch
// ---------------------------------------------------------------------------
struct DP { const uint32_t* W; const uint32_t* xT; const float* hi;
            const float* lo; float* d; int L; };

__global__ __launch_bounds__(256, 2)
void dec_s0_kernel(DP q3, DP q2, DP q1, MP ms0) {
    extern __shared__ uint32_t dynsm[];
    int bx = blockIdx.x;
    if (bx >= 512) {
        mkan_core(ms0, (bx - 512) * 128, dynsm, nullptr, nullptr);
        return;
    }
    DP p;
    int m0, b;
    if (bx < 256)      { p = q3; m0 = (bx >> 7) * 128; b = bx & 127; }
    else if (bx < 384) { p = q2; m0 = 0; b = bx - 256; }
    else               { p = q1; m0 = 0; b = bx - 384; }
    interp_odd_core(p.W, p.xT, p.hi, p.lo, p.d, nullptr,
                    p.L, -1.0f, m0, b, dynsm);
}

// ---------------------------------------------------------------------------
// mkan stages 3,2,1 (s1 with fused mix64 via Wx / xbT)
// ---------------------------------------------------------------------------
__global__ __launch_bounds__(256, 2)
void mkan_batched_kernel(MP s3, MP s2, MP s1,
                         const uint32_t* __restrict__ W64f,
                         const uint32_t* __restrict__ m64T) {
    extern __shared__ uint32_t dynsm[];
    int bx = blockIdx.x;
    if (bx < 512)      { mkan_core(s3, bx * 128, dynsm, nullptr, nullptr); }
    else if (bx < 768) { mkan_core(s2, (bx - 512) * 128, dynsm, nullptr, nullptr); }
    else {
        int m0 = (bx - 768) * 128;
        const uint32_t* xbT = m64T + (size_t)(m0 >> 7) * 128 * 64;
        mkan_core(s1, m0, dynsm, W64f, xbT);
    }
}

// ---------------------------------------------------------------------------
// mix: out = oh + interp(lo)
// ---------------------------------------------------------------------------
__global__ __launch_bounds__(256, 2)
void mix_odd_kernel(const uint32_t* __restrict__ W, const uint32_t* __restrict__ xT,
                    const float* __restrict__ oh, const float* __restrict__ lo,
                    float* __restrict__ out, uint32_t* __restrict__ xTout, int L) {
    extern __shared__ uint32_t dynsm[];
    interp_odd_core(W, xT, oh, lo, out, xTout,
                    L, 1.0f, blockIdx.x * 128, blockIdx.y, dynsm);
}

// ---------------------------------------------------------------------------
extern "C" void kernel_launch(void* const* d_in, const int* in_sizes, int n_in,
                              void* d_out, int out_size) {
    const float* x0 = (const float*)d_in[0];
    const float* x1 = (const float*)d_in[1];
    const float* x2 = (const float*)d_in[2];
    const float* x3 = (const float*)d_in[3];
    const float* c0 = (const float*)d_in[4];
    const float* w0 = (const float*)d_in[5];
    const float* c1 = (const float*)d_in[6];
    const float* w1 = (const float*)d_in[7];
    const float* c2 = (const float*)d_in[8];
    const float* w2 = (const float*)d_in[9];
    const float* c3 = (const float*)d_in[10];
    const float* w3 = (const float*)d_in[11];
    float* out = (float*)d_out;

    uint32_t *pW64, *pW128, *pW256, *pW64f, *pCt0, *pCt1, *pCt2, *pCt3, *pxT, *pxT2;
    float *pbias, *pd3, *pd2, *pd1, *poh2, *poh3;
    cudaGetSymbolAddress((void**)&pW64,  g_W64);
    cudaGetSymbolAddress((void**)&pW128, g_W128);
    cudaGetSymbolAddress((void**)&pW256, g_W256);
    cudaGetSymbolAddress((void**)&pW64f, g_W64f);
    cudaGetSymbolAddress((void**)&pCt0,  g_Ct0);
    cudaGetSymbolAddress((void**)&pCt1,  g_Ct1);
    cudaGetSymbolAddress((void**)&pCt2,  g_Ct2);
    cudaGetSymbolAddress((void**)&pCt3,  g_Ct3);
    cudaGetSymbolAddress((void**)&pbias, g_bias);
    cudaGetSymbolAddress((void**)&pd3,   g_d3);
    cudaGetSymbolAddress((void**)&pd2,   g_d2);
    cudaGetSymbolAddress((void**)&pd1,   g_d1);
    cudaGetSymbolAddress((void**)&poh2,  g_oh2);
    cudaGetSymbolAddress((void**)&poh3,  g_oh3);
    cudaGetSymbolAddress((void**)&pxT,   g_xT);
    cudaGetSymbolAddress((void**)&pxT2,  g_xT2);

    cudaFuncSetAttribute(dec_s0_kernel,
                         cudaFuncAttributeMaxDynamicSharedMemorySize, SMEM_BYTES_MKAN);
    cudaFuncSetAttribute(mkan_batched_kernel,
                         cudaFuncAttributeMaxDynamicSharedMemorySize, SMEM_BYTES_MKAN);
    cudaFuncSetAttribute(mix_odd_kernel,
                         cudaFuncAttributeMaxDynamicSharedMemorySize, SMEM_BYTES_INTERP);

    /*0*/ {
        PP p0 = {c0, pCt0, pbias + 0 * 128, 2};
        PP p1 = {c1, pCt1, pbias + 1 * 128, 3};
        PP p2 = {c2, pCt2, pbias + 2 * 128, 4};
        PP p3 = {c3, pCt3, pbias + 3 * 128, 5};
        setup_all_kernel<<<8048, 256>>>(pW256, pW128, pW64, pW64f,
                                        p0, p1, p2, p3, x1, x2, x3, pxT);
    }
    /*1*/ {
        DP q3 = {pW256, pxT + XT256_OFF, x0, x1, pd3, 256};
        DP q2 = {pW128, pxT + XT128_OFF, x1, x2, pd2, 128};
        DP q1 = {pW64,  pxT + XT64_OFF,  x2, x3, pd1, 64};
        MP ms0 = {pCt0, pbias + 0 * 128, x3, w0, out + OFF64, pxT2, 256, 64};
        dec_s0_kernel<<<576, 256, SMEM_BYTES_MKAN>>>(q3, q2, q1, ms0);
    }
    /*2*/ {
        MP s3 = {pCt3, pbias + 3 * 128, pd3, w3, poh3, nullptr, 640, 512};
        MP s2 = {pCt2, pbias + 2 * 128, pd2, w2, poh2, nullptr, 512, 256};
        MP s1 = {pCt1, pbias + 1 * 128, pd1, w1, out + OFF128, pxT, 384, 128};
        mkan_batched_kernel<<<896, 256, SMEM_BYTES_MKAN>>>(s3, s2, s1, pW64f, pxT2);
    }
    /*3*/ mix_odd_kernel<<<dim3(1, 128), 256, SMEM_BYTES_INTERP>>>(
              pW128, pxT, poh2, out + OFF128, out + OFF256, pxT2, 128);
    /*4*/ mix_odd_kernel<<<dim3(2, 128), 256, SMEM_BYTES_INTERP>>>(
              pW256, pxT2, poh3, out + OFF256, out + OFF512, nullptr, 256);

    (void)in_sizes; (void)n_in; (void)out_size;
}